// round 5
// baseline (speedup 1.0000x reference)
#include <cuda_runtime.h>
#include <math.h>

// ---------------- fixed problem dims ----------------
#define BATCH 2
#define SEQ   2048
#define TCNT  4096        // BATCH*SEQ
#define IND   512
#define ED    1024
#define INNER 2048
#define UP2   4096        // 2*INNER
#define NH    4
#define DH    512
#define NHW   512
#define ZB    8           // BATCH*NH

// ---------------- scratch (bss, no allocation) ----------------
__device__ float g_hin[TCNT*ED];
__device__ float g_xn [TCNT*ED];
__device__ float g_up [(size_t)TCNT*UP2];
__device__ float g_xca[TCNT*INNER];
__device__ float g_q  [TCNT*INNER];
__device__ float g_k  [TCNT*INNER];
__device__ float g_v  [TCNT*INNER];
__device__ float g_ig [ZB*SEQ];
__device__ float g_fg [ZB*SEQ];
__device__ float g_cum[ZB*SEQ];
__device__ float g_m  [ZB*SEQ];
__device__ float g_in2[ZB*SEQ];
__device__ float g_C  [(size_t)ZB*SEQ*SEQ];    // 128 MB
__device__ float g_h  [(size_t)ZB*SEQ*DH];
__device__ float g_g  [TCNT*INNER];
__device__ float g_yt [TCNT*ED];

// ---------------- helpers ----------------
__device__ __forceinline__ float blockReduceSum(float v, float* sm) {
    int tid = threadIdx.x;
    __syncthreads();
    #pragma unroll
    for (int o = 16; o > 0; o >>= 1) v += __shfl_down_sync(0xffffffffu, v, o);
    if ((tid & 31) == 0) sm[tid >> 5] = v;
    __syncthreads();
    int nw = blockDim.x >> 5;
    float r = (tid < nw) ? sm[tid] : 0.f;
    if (tid < 32) {
        #pragma unroll
        for (int o = 16; o > 0; o >>= 1) r += __shfl_down_sync(0xffffffffu, r, o);
        if (tid == 0) sm[0] = r;
    }
    __syncthreads();
    return sm[0];
}

// ---------------- SGEMM 128x128x8, 256 threads, 8x8 microtile ----------------
// EPI 0: C = A@B + bias[n]
// EPI 1: C = A@B + bias[n] + addm[m,n]
// EPI 2: batched per-head qk:  C = (A@B^T/sqrt(DH)) * exp(cum_i - cum_j + ig_j - m_i), j<=i else 0
// EPI 3: batched per-head C@v with causal k-limit, row-scaled by invn[i]
#define BM 128
#define BN 128
#define BK 8

template<int EPI>
__global__ void __launch_bounds__(256, 2)
sgemm(const float* __restrict__ Ag, const float* __restrict__ Bg, float* __restrict__ Cg,
      int M, int N, int K, int lda, int ldb, int ldc,
      const float* __restrict__ bias, const float* __restrict__ addm,
      const float* __restrict__ cumv, const float* __restrict__ igv,
      const float* __restrict__ mvv,  const float* __restrict__ invn)
{
    const int m0 = blockIdx.y * BM;
    const int n0 = blockIdx.x * BN;
    if (EPI == 2 && n0 > m0) return;                  // strictly above diagonal
    const int z = blockIdx.z;

    const float* A = Ag; const float* Bp = Bg; float* C = Cg;
    if (EPI == 2) {
        int b = z >> 2, h = z & 3;
        A  = Ag + ((size_t)b*SEQ)*INNER + h*DH;       // q head slice
        Bp = Bg + ((size_t)b*SEQ)*INNER + h*DH;       // k head slice (B^T form)
        C  = Cg + (size_t)z*SEQ*SEQ;
    } else if (EPI == 3) {
        int b = z >> 2, h = z & 3;
        A  = Ag + (size_t)z*SEQ*SEQ;                  // Cmat
        Bp = Bg + ((size_t)b*SEQ)*INNER + h*DH;       // v head slice
        C  = Cg + (size_t)z*SEQ*DH;
    }
    const int kend = (EPI == 3) ? (m0 + BM) : K;

    __shared__ float As[BK][BM];
    __shared__ float Bs[BK][BN];

    const int tid  = threadIdx.x;
    const int tx   = tid & 15, ty = tid >> 4;
    const int aRow = tid >> 1, aCol = (tid & 1) * 4;
    const int bRow = tid >> 5, bCol = (tid & 31) * 4;

    float acc[8][8];
    #pragma unroll
    for (int i = 0; i < 8; i++)
        #pragma unroll
        for (int j = 0; j < 8; j++) acc[i][j] = 0.f;

    for (int k0 = 0; k0 < kend; k0 += BK) {
        float4 av = *(const float4*)(A + (size_t)(m0 + aRow)*lda + (k0 + aCol));
        As[aCol+0][aRow] = av.x; As[aCol+1][aRow] = av.y;
        As[aCol+2][aRow] = av.z; As[aCol+3][aRow] = av.w;
        if (EPI == 2) {
            float4 bv = *(const float4*)(Bp + (size_t)(n0 + aRow)*ldb + (k0 + aCol));
            Bs[aCol+0][aRow] = bv.x; Bs[aCol+1][aRow] = bv.y;
            Bs[aCol+2][aRow] = bv.z; Bs[aCol+3][aRow] = bv.w;
        } else {
            float4 bv = *(const float4*)(Bp + (size_t)(k0 + bRow)*ldb + (n0 + bCol));
            *(float4*)&Bs[bRow][bCol] = bv;
        }
        __syncthreads();
        #pragma unroll
        for (int kk = 0; kk < BK; kk++) {
            float a[8], b[8];
            *(float4*)(a)   = *(const float4*)&As[kk][ty*4];
            *(float4*)(a+4) = *(const float4*)&As[kk][64 + ty*4];
            *(float4*)(b)   = *(const float4*)&Bs[kk][tx*4];
            *(float4*)(b+4) = *(const float4*)&Bs[kk][64 + tx*4];
            #pragma unroll
            for (int i = 0; i < 8; i++)
                #pragma unroll
                for (int j = 0; j < 8; j++)
                    acc[i][j] = fmaf(a[i], b[j], acc[i][j]);
        }
        __syncthreads();
    }

    if (EPI == 0 || EPI == 1) {
        #pragma unroll
        for (int ih = 0; ih < 2; ih++)
        #pragma unroll
        for (int i = 0; i < 4; i++) {
            int m = m0 + ih*64 + ty*4 + i;
            #pragma unroll
            for (int jh = 0; jh < 2; jh++) {
                int n = n0 + jh*64 + tx*4;
                float4 bv = *(const float4*)(bias + n);
                float4 r;
                r.x = acc[ih*4+i][jh*4+0] + bv.x;
                r.y = acc[ih*4+i][jh*4+1] + bv.y;
                r.z = acc[ih*4+i][jh*4+2] + bv.z;
                r.w = acc[ih*4+i][jh*4+3] + bv.w;
                if (EPI == 1) {
                    float4 ad = *(const float4*)(addm + (size_t)m*ldc + n);
                    r.x += ad.x; r.y += ad.y; r.z += ad.z; r.w += ad.w;
                }
                *(float4*)(C + (size_t)m*ldc + n) = r;
            }
        }
    } else if (EPI == 2) {
        const float* cu = cumv + z*SEQ;
        const float* ip = igv  + z*SEQ;
        const float* mp = mvv  + z*SEQ;
        float cj[8], ij8[8];
        #pragma unroll
        for (int jh = 0; jh < 2; jh++)
            #pragma unroll
            for (int j = 0; j < 4; j++) {
                int n = n0 + jh*64 + tx*4 + j;
                cj [jh*4+j] = cu[n];
                ij8[jh*4+j] = ip[n];
            }
        const float SC = 0.04419417382415922f; // 1/sqrt(512)
        #pragma unroll
        for (int ih = 0; ih < 2; ih++)
        #pragma unroll
        for (int i = 0; i < 4; i++) {
            int m = m0 + ih*64 + ty*4 + i;
            float ci = cu[m], mi = mp[m];
            #pragma unroll
            for (int jh = 0; jh < 2; jh++) {
                int n = n0 + jh*64 + tx*4;
                float4 r;
                r.x = (n+0 <= m) ? acc[ih*4+i][jh*4+0]*SC*__expf(ci - cj[jh*4+0] + ij8[jh*4+0] - mi) : 0.f;
                r.y = (n+1 <= m) ? acc[ih*4+i][jh*4+1]*SC*__expf(ci - cj[jh*4+1] + ij8[jh*4+1] - mi) : 0.f;
                r.z = (n+2 <= m) ? acc[ih*4+i][jh*4+2]*SC*__expf(ci - cj[jh*4+2] + ij8[jh*4+2] - mi) : 0.f;
                r.w = (n+3 <= m) ? acc[ih*4+i][jh*4+3]*SC*__expf(ci - cj[jh*4+3] + ij8[jh*4+3] - mi) : 0.f;
                *(float4*)(C + (size_t)m*ldc + n) = r;
            }
        }
    } else { // EPI 3
        const float* iv = invn + z*SEQ;
        #pragma unroll
        for (int ih = 0; ih < 2; ih++)
        #pragma unroll
        for (int i = 0; i < 4; i++) {
            int m = m0 + ih*64 + ty*4 + i;
            float s = iv[m];
            #pragma unroll
            for (int jh = 0; jh < 2; jh++) {
                int n = n0 + jh*64 + tx*4;
                float4 r;
                r.x = acc[ih*4+i][jh*4+0] * s;
                r.y = acc[ih*4+i][jh*4+1] * s;
                r.z = acc[ih*4+i][jh*4+2] * s;
                r.w = acc[ih*4+i][jh*4+3] * s;
                *(float4*)(C + (size_t)m*ldc + n) = r;
            }
        }
    }
}

// ---------------- LayerNorm (width 1024, weight only, eps 1e-5) ----------------
__global__ void ln_kernel(const float* __restrict__ x, const float* __restrict__ w,
                          float* __restrict__ y)
{
    int r = blockIdx.x, tid = threadIdx.x;   // 256 threads
    const float* xr = x + (size_t)r*ED;
    float4 v = *(const float4*)(xr + tid*4);
    float s = v.x + v.y + v.z + v.w;
    float q = v.x*v.x + v.y*v.y + v.z*v.z + v.w*v.w;
    __shared__ float sm[8];
    s = blockReduceSum(s, sm);
    q = blockReduceSum(q, sm);
    float mean = s * (1.f/ED);
    float var  = q * (1.f/ED) - mean*mean;
    float rstd = rsqrtf(var + 1e-5f);
    float4 wv = *(const float4*)(w + tid*4);
    float4 o;
    o.x = (v.x - mean)*rstd*wv.x; o.y = (v.y - mean)*rstd*wv.y;
    o.z = (v.z - mean)*rstd*wv.z; o.w = (v.w - mean)*rstd*wv.w;
    *(float4*)(y + (size_t)r*ED + tid*4) = o;
}

// ---------------- causal depthwise conv (K=4) + SiLU ----------------
__global__ void conv_silu_kernel(const float* __restrict__ up, const float* __restrict__ cw,
                                 const float* __restrict__ cb, float* __restrict__ xca)
{
    int idx = blockIdx.x*256 + threadIdx.x;   // < TCNT*INNER
    int c = idx & (INNER-1);
    int t = idx >> 11;
    int s = t & (SEQ-1);
    float acc = cb[c];
    const float* w = cw + c*4;
    #pragma unroll
    for (int kk = 0; kk < 4; kk++) {
        int ss = s - 3 + kk;
        if (ss >= 0) acc = fmaf(up[(size_t)(t - 3 + kk)*UP2 + c], w[kk], acc);
    }
    xca[idx] = acc / (1.f + __expf(-acc));
}

// ---------------- 4x4 block-diagonal q/k/v projections ----------------
__global__ void headwise_kernel(const float* __restrict__ xca, const float* __restrict__ up,
    const float* __restrict__ qw, const float* __restrict__ qb,
    const float* __restrict__ kw, const float* __restrict__ kb,
    const float* __restrict__ vw, const float* __restrict__ vb,
    float* __restrict__ q, float* __restrict__ k, float* __restrict__ v)
{
    int idx = blockIdx.x*256 + threadIdx.x;   // < TCNT*NHW
    int hb = idx & (NHW-1);
    int t  = idx >> 9;
    int co = hb*4;
    float4 xc = *(const float4*)(xca + (size_t)t*INNER + co);
    float4 xm = *(const float4*)(up  + (size_t)t*UP2   + co);
    float xcv[4] = {xc.x, xc.y, xc.z, xc.w};
    float xmv[4] = {xm.x, xm.y, xm.z, xm.w};
    const float* qwp = qw + hb*16;
    const float* kwp = kw + hb*16;
    const float* vwp = vw + hb*16;
    float qo[4], ko[4], vo[4];
    #pragma unroll
    for (int o = 0; o < 4; o++) {
        float aq = qb[co+o], ak = kb[co+o], av = vb[co+o];
        #pragma unroll
        for (int d = 0; d < 4; d++) {
            aq = fmaf(xcv[d], qwp[o*4+d], aq);
            ak = fmaf(xcv[d], kwp[o*4+d], ak);
            av = fmaf(xmv[d], vwp[o*4+d], av);
        }
        qo[o] = aq; ko[o] = ak; vo[o] = av;
    }
    *(float4*)(q + (size_t)t*INNER + co) = make_float4(qo[0],qo[1],qo[2],qo[3]);
    *(float4*)(k + (size_t)t*INNER + co) = make_float4(ko[0],ko[1],ko[2],ko[3]);
    *(float4*)(v + (size_t)t*INNER + co) = make_float4(vo[0],vo[1],vo[2],vo[3]);
}

// ---------------- gate projections: ig/fg = concat(q,k,v) @ W(6144,4) ----------------
__global__ void gates_kernel(const float* __restrict__ q, const float* __restrict__ k,
    const float* __restrict__ v,
    const float* __restrict__ igw, const float* __restrict__ igb,
    const float* __restrict__ fgw, const float* __restrict__ fgb,
    float* __restrict__ igo, float* __restrict__ fgo)
{
    int t = blockIdx.x, tid = threadIdx.x;
    float li[4] = {0,0,0,0}, lf[4] = {0,0,0,0};
    for (int c = tid; c < 3*INNER; c += 256) {
        int cc = c & (INNER-1);
        float xv = (c < INNER) ? q[(size_t)t*INNER + cc]
                 : (c < 2*INNER) ? k[(size_t)t*INNER + cc]
                 : v[(size_t)t*INNER + cc];
        float4 wi = *(const float4*)(igw + c*4);
        float4 wf = *(const float4*)(fgw + c*4);
        li[0] = fmaf(xv, wi.x, li[0]); li[1] = fmaf(xv, wi.y, li[1]);
        li[2] = fmaf(xv, wi.z, li[2]); li[3] = fmaf(xv, wi.w, li[3]);
        lf[0] = fmaf(xv, wf.x, lf[0]); lf[1] = fmaf(xv, wf.y, lf[1]);
        lf[2] = fmaf(xv, wf.z, lf[2]); lf[3] = fmaf(xv, wf.w, lf[3]);
    }
    __shared__ float red[256*8];
    #pragma unroll
    for (int n = 0; n < 4; n++) { red[tid*8+n] = li[n]; red[tid*8+4+n] = lf[n]; }
    __syncthreads();
    for (int off = 128; off >= 1; off >>= 1) {
        if (tid < off)
            #pragma unroll
            for (int n = 0; n < 8; n++) red[tid*8+n] += red[(tid+off)*8+n];
        __syncthreads();
    }
    if (tid < 4) {
        int b = t >> 11, s = t & (SEQ-1);
        igo[(b*NH + tid)*SEQ + s] = red[tid]   + igb[tid];
        fgo[(b*NH + tid)*SEQ + s] = red[4+tid] + fgb[tid];
    }
}

// ---------------- per-head scans: cum = cumsum(logsigmoid(fg)), m = cum + runmax(ig - cum) ----------------
__global__ void scan_kernel(const float* __restrict__ fgv, const float* __restrict__ igv,
                            float* __restrict__ cumv, float* __restrict__ mvv)
{
    int z = blockIdx.x, tid = threadIdx.x;   // 256 threads
    __shared__ float sc[SEQ];
    __shared__ float sa[SEQ];
    __shared__ float aux[256];
    const float* fg = fgv + z*SEQ;
    const float* ig = igv + z*SEQ;
    for (int s = tid; s < SEQ; s += 256) {
        float xx = fg[s];
        sc[s] = (xx >= 0.f) ? -log1pf(expf(-xx)) : (xx - log1pf(expf(xx)));
    }
    __syncthreads();
    { // inclusive sum scan
        float vloc[8]; float run = 0.f; int base = tid*8;
        #pragma unroll
        for (int i = 0; i < 8; i++) { run += sc[base+i]; vloc[i] = run; }
        aux[tid] = run;
        __syncthreads();
        for (int off = 1; off < 256; off <<= 1) {
            float add = (tid >= off) ? aux[tid-off] : 0.f;
            __syncthreads();
            aux[tid] += add;
            __syncthreads();
        }
        float pre = (tid > 0) ? aux[tid-1] : 0.f;
        #pragma unroll
        for (int i = 0; i < 8; i++) sc[base+i] = vloc[i] + pre;
    }
    __syncthreads();
    for (int s = tid; s < SEQ; s += 256) sa[s] = ig[s] - sc[s];
    __syncthreads();
    { // inclusive max scan
        float vloc[8]; float run = -INFINITY; int base = tid*8;
        #pragma unroll
        for (int i = 0; i < 8; i++) { run = fmaxf(run, sa[base+i]); vloc[i] = run; }
        aux[tid] = run;
        __syncthreads();
        for (int off = 1; off < 256; off <<= 1) {
            float add = (tid >= off) ? aux[tid-off] : -INFINITY;
            __syncthreads();
            aux[tid] = fmaxf(aux[tid], add);
            __syncthreads();
        }
        float pre = (tid > 0) ? aux[tid-1] : -INFINITY;
        #pragma unroll
        for (int i = 0; i < 8; i++) sa[base+i] = fmaxf(vloc[i], pre);
    }
    __syncthreads();
    for (int s = tid; s < SEQ; s += 256) {
        cumv[z*SEQ + s] = sc[s];
        mvv [z*SEQ + s] = sc[s] + sa[s];
    }
}

// ---------------- masked row-sum of C -> 1/(max(|sum|, exp(-m)) + eps) ----------------
__global__ void rowsum_kernel(const float* __restrict__ Cm, const float* __restrict__ mvv,
                              float* __restrict__ invn)
{
    int row = blockIdx.x;                    // z*SEQ + i, contiguous with Cm layout
    int i = row & (SEQ-1);
    const float* cr = Cm + (size_t)row*SEQ;
    float s = 0.f;
    for (int j = threadIdx.x; j <= i; j += 256) s += cr[j];
    __shared__ float sm[8];
    s = blockReduceSum(s, sm);
    if (threadIdx.x == 0) {
        float m   = mvv[row];
        float nrm = fmaxf(fabsf(s), expf(-m));
        invn[row] = 1.f / (nrm + 1e-6f);
    }
}

// ---------------- head-norm + skip + output gate ----------------
__global__ void headnorm_gate_kernel(const float* __restrict__ hb_, const float* __restrict__ ow,
    const float* __restrict__ skipv, const float* __restrict__ xca,
    const float* __restrict__ up, float* __restrict__ g)
{
    int idx = blockIdx.x;                    // t*NH + h
    int h = idx & 3, t = idx >> 2;
    int b = t >> 11, s = t & (SEQ-1);
    const float* hr = hb_ + ((size_t)(b*NH + h)*SEQ + s)*DH;
    int tid = threadIdx.x;                   // 128 threads * 4 = 512
    float4 hv = *(const float4*)(hr + tid*4);
    float sum = hv.x + hv.y + hv.z + hv.w;
    float sq  = hv.x*hv.x + hv.y*hv.y + hv.z*hv.z + hv.w*hv.w;
    __shared__ float sm[4];
    sum = blockReduceSum(sum, sm);
    sq  = blockReduceSum(sq, sm);
    float mean = sum * (1.f/DH);
    float var  = sq * (1.f/DH) - mean*mean;
    float rstd = rsqrtf(var + 1e-5f);
    int c = h*DH + tid*4;
    float4 owv = *(const float4*)(ow + c);
    float4 sk  = *(const float4*)(skipv + c);
    float4 xc  = *(const float4*)(xca + (size_t)t*INNER + c);
    float4 zv  = *(const float4*)(up + (size_t)t*UP2 + INNER + c);
    float4 o;
    o.x = ((hv.x-mean)*rstd*owv.x + sk.x*xc.x) * (zv.x / (1.f + __expf(-zv.x)));
    o.y = ((hv.y-mean)*rstd*owv.y + sk.y*xc.y) * (zv.y / (1.f + __expf(-zv.y)));
    o.z = ((hv.z-mean)*rstd*owv.z + sk.z*xc.z) * (zv.z / (1.f + __expf(-zv.z)));
    o.w = ((hv.w-mean)*rstd*owv.w + sk.w*xc.w) * (zv.w / (1.f + __expf(-zv.w)));
    *(float4*)(g + (size_t)t*INNER + c) = o;
}

// ---------------- launch ----------------
extern "C" void kernel_launch(void* const* d_in, const int* in_sizes, int n_in,
                              void* d_out, int out_size)
{
    const float* x      = (const float*)d_in[0];
    const float* w_in   = (const float*)d_in[1];
    const float* b_in   = (const float*)d_in[2];
    const float* ln1_w  = (const float*)d_in[3];
    const float* w_up   = (const float*)d_in[4];
    const float* b_up   = (const float*)d_in[5];
    const float* conv_w = (const float*)d_in[6];
    const float* conv_b = (const float*)d_in[7];
    const float* q_w    = (const float*)d_in[8];
    const float* q_b    = (const float*)d_in[9];
    const float* k_w    = (const float*)d_in[10];
    const float* k_b    = (const float*)d_in[11];
    const float* v_w    = (const float*)d_in[12];
    const float* v_b    = (const float*)d_in[13];
    const float* ig_w   = (const float*)d_in[14];
    const float* ig_b   = (const float*)d_in[15];
    const float* fg_w   = (const float*)d_in[16];
    const float* fg_b   = (const float*)d_in[17];
    const float* onorm_w= (const float*)d_in[18];
    const float* skipv  = (const float*)d_in[19];
    const float* w_down = (const float*)d_in[20];
    const float* b_down = (const float*)d_in[21];
    const float* post_w = (const float*)d_in[22];

    static float *p_hin=nullptr,*p_xn,*p_up,*p_xca,*p_q,*p_k,*p_v,*p_ig,*p_fg,
                 *p_cum,*p_m,*p_in2,*p_C,*p_h,*p_g,*p_yt;
    if (!p_hin) {
        cudaGetSymbolAddress((void**)&p_hin, g_hin);
        cudaGetSymbolAddress((void**)&p_xn , g_xn );
        cudaGetSymbolAddress((void**)&p_up , g_up );
        cudaGetSymbolAddress((void**)&p_xca, g_xca);
        cudaGetSymbolAddress((void**)&p_q  , g_q  );
        cudaGetSymbolAddress((void**)&p_k  , g_k  );
        cudaGetSymbolAddress((void**)&p_v  , g_v  );
        cudaGetSymbolAddress((void**)&p_ig , g_ig );
        cudaGetSymbolAddress((void**)&p_fg , g_fg );
        cudaGetSymbolAddress((void**)&p_cum, g_cum);
        cudaGetSymbolAddress((void**)&p_m  , g_m  );
        cudaGetSymbolAddress((void**)&p_in2, g_in2);
        cudaGetSymbolAddress((void**)&p_C  , g_C  );
        cudaGetSymbolAddress((void**)&p_h  , g_h  );
        cudaGetSymbolAddress((void**)&p_g  , g_g  );
        cudaGetSymbolAddress((void**)&p_yt , g_yt );
    }

    // 1) h_in = x @ w_in + b_in
    sgemm<0><<<dim3(ED/128, TCNT/128, 1), 256>>>(x, w_in, p_hin, TCNT, ED, IND,
        IND, ED, ED, b_in, nullptr, nullptr, nullptr, nullptr, nullptr);
    // 2) xn = LN(h_in)*ln1_w
    ln_kernel<<<TCNT, 256>>>(p_hin, ln1_w, p_xn);
    // 3) up = xn @ w_up + b_up
    sgemm<0><<<dim3(UP2/128, TCNT/128, 1), 256>>>(p_xn, w_up, p_up, TCNT, UP2, ED,
        ED, UP2, UP2, b_up, nullptr, nullptr, nullptr, nullptr, nullptr);
    // 4) causal conv + SiLU
    conv_silu_kernel<<<(TCNT*INNER)/256, 256>>>(p_up, conv_w, conv_b, p_xca);
    // 5) block-diagonal q/k/v
    headwise_kernel<<<(TCNT*NHW)/256, 256>>>(p_xca, p_up, q_w, q_b, k_w, k_b, v_w, v_b,
                                             p_q, p_k, p_v);
    // 6) gates
    gates_kernel<<<TCNT, 256>>>(p_q, p_k, p_v, ig_w, ig_b, fg_w, fg_b, p_ig, p_fg);
    // 7) per-head scans (cum, m)
    scan_kernel<<<ZB, 256>>>(p_fg, p_ig, p_cum, p_m);
    // 8) C = (q@k^T/sqrt(DH)) * decay, causal
    sgemm<2><<<dim3(SEQ/128, SEQ/128, ZB), 256>>>(p_q, p_k, p_C, SEQ, SEQ, DH,
        INNER, INNER, SEQ, nullptr, nullptr, p_cum, p_ig, p_m, nullptr);
    // 9) row normalizer
    rowsum_kernel<<<ZB*SEQ, 256>>>(p_C, p_m, p_in2);
    // 10) h = diag(invn) * C @ v
    sgemm<3><<<dim3(DH/128, SEQ/128, ZB), 256>>>(p_C, p_v, p_h, SEQ, DH, SEQ,
        SEQ, INNER, DH, nullptr, nullptr, nullptr, nullptr, nullptr, p_in2);
    // 11) head-norm + skip + output gate
    headnorm_gate_kernel<<<TCNT*NH, 128>>>(p_h, onorm_w, skipv, p_xca, p_up, p_g);
    // 12) yt = g @ w_down + b_down + h_in
    sgemm<1><<<dim3(ED/128, TCNT/128, 1), 256>>>(p_g, w_down, p_yt, TCNT, ED, INNER,
        INNER, ED, ED, b_down, p_hin, nullptr, nullptr, nullptr, nullptr);
    // 13) out = LN(yt)*post_w
    ln_kernel<<<TCNT, 256>>>(p_yt, post_w, (float*)d_out);
}

// round 8
// speedup vs baseline: 1.0800x; 1.0800x over previous
#include <cuda_runtime.h>
#include <math.h>

// ---------------- fixed problem dims ----------------
#define BATCH 2
#define SEQ   2048
#define TCNT  4096        // BATCH*SEQ
#define IND   512
#define ED    1024
#define INNER 2048
#define UP2   4096        // 2*INNER
#define NH    4
#define DH    512
#define NHW   512
#define ZB    8           // BATCH*NH

// ---------------- scratch (bss, no allocation) ----------------
__device__ float g_hin[TCNT*ED];
__device__ float g_xn [TCNT*ED];
__device__ float g_up [(size_t)TCNT*UP2];
__device__ float g_xca[TCNT*INNER];
__device__ float g_q  [TCNT*INNER];
__device__ float g_k  [TCNT*INNER];
__device__ float g_v  [TCNT*INNER];
__device__ float g_ig [ZB*SEQ];
__device__ float g_fg [ZB*SEQ];
__device__ float g_cum[ZB*SEQ];
__device__ float g_m  [ZB*SEQ];
__device__ float g_in2[ZB*SEQ];
__device__ float g_C  [(size_t)ZB*SEQ*SEQ];    // 128 MB
__device__ float g_h  [(size_t)ZB*SEQ*DH];
__device__ float g_g  [TCNT*INNER];
__device__ float g_yt [TCNT*ED];

// ---------------- helpers ----------------
__device__ __forceinline__ float blockReduceSum(float v, float* sm) {
    int tid = threadIdx.x;
    __syncthreads();
    #pragma unroll
    for (int o = 16; o > 0; o >>= 1) v += __shfl_down_sync(0xffffffffu, v, o);
    if ((tid & 31) == 0) sm[tid >> 5] = v;
    __syncthreads();
    int nw = blockDim.x >> 5;
    float r = (tid < nw) ? sm[tid] : 0.f;
    if (tid < 32) {
        #pragma unroll
        for (int o = 16; o > 0; o >>= 1) r += __shfl_down_sync(0xffffffffu, r, o);
        if (tid == 0) sm[0] = r;
    }
    __syncthreads();
    return sm[0];
}

__device__ __forceinline__ float lo32(unsigned long long v){ return __uint_as_float((unsigned)v); }
__device__ __forceinline__ float hi32(unsigned long long v){ return __uint_as_float((unsigned)(v>>32)); }

// ---------------- SGEMM 128x128x8, 256 threads, 8x8 microtile, packed f32x2 FMA ----------------
// EPI 0: C = A@B + bias[n]
// EPI 1: C = A@B + bias[n] + addm[m,n]
// EPI 2: batched per-head qk:  C = (A@B^T/sqrt(DH)) * exp(cum_i - cum_j + ig_j - m_i), j<=i else 0
// EPI 3: batched per-head C@v with causal k-limit, row-scaled by invn[i]
#define BM 128
#define BN 128
#define BK 8

template<int EPI>
__global__ void __launch_bounds__(256, 2)
sgemm(const float* __restrict__ Ag, const float* __restrict__ Bg, float* __restrict__ Cg,
      int M, int N, int K, int lda, int ldb, int ldc,
      const float* __restrict__ bias, const float* __restrict__ addm,
      const float* __restrict__ cumv, const float* __restrict__ igv,
      const float* __restrict__ mvv,  const float* __restrict__ invn)
{
    const int m0 = blockIdx.y * BM;
    const int n0 = blockIdx.x * BN;
    if (EPI == 2 && n0 > m0) return;                  // strictly above diagonal
    const int z = blockIdx.z;

    const float* A = Ag; const float* Bp = Bg; float* C = Cg;
    if (EPI == 2) {
        int b = z >> 2, h = z & 3;
        A  = Ag + ((size_t)b*SEQ)*INNER + h*DH;       // q head slice
        Bp = Bg + ((size_t)b*SEQ)*INNER + h*DH;       // k head slice (B^T form)
        C  = Cg + (size_t)z*SEQ*SEQ;
    } else if (EPI == 3) {
        int b = z >> 2, h = z & 3;
        A  = Ag + (size_t)z*SEQ*SEQ;                  // Cmat
        Bp = Bg + ((size_t)b*SEQ)*INNER + h*DH;       // v head slice
        C  = Cg + (size_t)z*SEQ*DH;
    }
    const int kend = (EPI == 3) ? (m0 + BM) : K;

    __shared__ __align__(16) float As[BK][BM];
    __shared__ __align__(16) float Bs[BK][BN];

    const int tid  = threadIdx.x;
    const int tx   = tid & 15, ty = tid >> 4;
    const int aRow = tid >> 1, aCol = (tid & 1) * 4;
    const int bRow = tid >> 5, bCol = (tid & 31) * 4;

    // acc2[i][p] = packed pair of columns (2p, 2p+1) within the 8-col microtile
    unsigned long long acc2[8][4];
    #pragma unroll
    for (int i = 0; i < 8; i++)
        #pragma unroll
        for (int j = 0; j < 4; j++) acc2[i][j] = 0ull;

    for (int k0 = 0; k0 < kend; k0 += BK) {
        float4 av = *(const float4*)(A + (size_t)(m0 + aRow)*lda + (k0 + aCol));
        As[aCol+0][aRow] = av.x; As[aCol+1][aRow] = av.y;
        As[aCol+2][aRow] = av.z; As[aCol+3][aRow] = av.w;
        if (EPI == 2) {
            float4 bv = *(const float4*)(Bp + (size_t)(n0 + aRow)*ldb + (k0 + aCol));
            Bs[aCol+0][aRow] = bv.x; Bs[aCol+1][aRow] = bv.y;
            Bs[aCol+2][aRow] = bv.z; Bs[aCol+3][aRow] = bv.w;
        } else {
            float4 bv = *(const float4*)(Bp + (size_t)(k0 + bRow)*ldb + (n0 + bCol));
            *(float4*)&Bs[bRow][bCol] = bv;
        }
        __syncthreads();
        #pragma unroll
        for (int kk = 0; kk < BK; kk++) {
            float a[8];
            *(float4*)(a)   = *(const float4*)&As[kk][ty*4];
            *(float4*)(a+4) = *(const float4*)&As[kk][64 + ty*4];
            unsigned long long bp[4];
            *(ulonglong2*)(bp)     = *(const ulonglong2*)&Bs[kk][tx*4];
            *(ulonglong2*)(bp + 2) = *(const ulonglong2*)&Bs[kk][64 + tx*4];
            unsigned long long ap[8];
            #pragma unroll
            for (int i = 0; i < 8; i++) {
                unsigned u = __float_as_uint(a[i]);
                asm("mov.b64 %0, {%1, %1};" : "=l"(ap[i]) : "r"(u));
            }
            #pragma unroll
            for (int i = 0; i < 8; i++)
                #pragma unroll
                for (int j = 0; j < 4; j++)
                    asm("fma.rn.f32x2 %0, %1, %2, %0;"
                        : "+l"(acc2[i][j]) : "l"(ap[i]), "l"(bp[j]));
        }
        __syncthreads();
    }

    if (EPI == 0 || EPI == 1) {
        #pragma unroll
        for (int ih = 0; ih < 2; ih++)
        #pragma unroll
        for (int i = 0; i < 4; i++) {
            int m = m0 + ih*64 + ty*4 + i;
            int row = ih*4 + i;
            #pragma unroll
            for (int jh = 0; jh < 2; jh++) {
                int n = n0 + jh*64 + tx*4;
                float4 bv = *(const float4*)(bias + n);
                float4 r;
                r.x = lo32(acc2[row][jh*2+0]) + bv.x;
                r.y = hi32(acc2[row][jh*2+0]) + bv.y;
                r.z = lo32(acc2[row][jh*2+1]) + bv.z;
                r.w = hi32(acc2[row][jh*2+1]) + bv.w;
                if (EPI == 1) {
                    float4 ad = *(const float4*)(addm + (size_t)m*ldc + n);
                    r.x += ad.x; r.y += ad.y; r.z += ad.z; r.w += ad.w;
                }
                *(float4*)(C + (size_t)m*ldc + n) = r;
            }
        }
    } else if (EPI == 2) {
        const float* cu = cumv + z*SEQ;
        const float* ip = igv  + z*SEQ;
        const float* mp = mvv  + z*SEQ;
        float cj[8], ij8[8];
        #pragma unroll
        for (int jh = 0; jh < 2; jh++)
            #pragma unroll
            for (int j = 0; j < 4; j++) {
                int n = n0 + jh*64 + tx*4 + j;
                cj [jh*4+j] = cu[n];
                ij8[jh*4+j] = ip[n];
            }
        const float SC = 0.04419417382415922f; // 1/sqrt(512)
        #pragma unroll
        for (int ih = 0; ih < 2; ih++)
        #pragma unroll
        for (int i = 0; i < 4; i++) {
            int m = m0 + ih*64 + ty*4 + i;
            int row = ih*4 + i;
            float ci = cu[m], mi = mp[m];
            #pragma unroll
            for (int jh = 0; jh < 2; jh++) {
                int n = n0 + jh*64 + tx*4;
                float4 r;
                r.x = (n+0 <= m) ? lo32(acc2[row][jh*2+0])*SC*__expf(ci - cj[jh*4+0] + ij8[jh*4+0] - mi) : 0.f;
                r.y = (n+1 <= m) ? hi32(acc2[row][jh*2+0])*SC*__expf(ci - cj[jh*4+1] + ij8[jh*4+1] - mi) : 0.f;
                r.z = (n+2 <= m) ? lo32(acc2[row][jh*2+1])*SC*__expf(ci - cj[jh*4+2] + ij8[jh*4+2] - mi) : 0.f;
                r.w = (n+3 <= m) ? hi32(acc2[row][jh*2+1])*SC*__expf(ci - cj[jh*4+3] + ij8[jh*4+3] - mi) : 0.f;
                *(float4*)(C + (size_t)m*ldc + n) = r;
            }
        }
    } else { // EPI 3
        const float* iv = invn + z*SEQ;
        #pragma unroll
        for (int ih = 0; ih < 2; ih++)
        #pragma unroll
        for (int i = 0; i < 4; i++) {
            int m = m0 + ih*64 + ty*4 + i;
            int row = ih*4 + i;
            float s = iv[m];
            #pragma unroll
            for (int jh = 0; jh < 2; jh++) {
                int n = n0 + jh*64 + tx*4;
                float4 r;
                r.x = lo32(acc2[row][jh*2+0]) * s;
                r.y = hi32(acc2[row][jh*2+0]) * s;
                r.z = lo32(acc2[row][jh*2+1]) * s;
                r.w = hi32(acc2[row][jh*2+1]) * s;
                *(float4*)(C + (size_t)m*ldc + n) = r;
            }
        }
    }
}

// ---------------- LayerNorm (width 1024, weight only, eps 1e-5) ----------------
__global__ void ln_kernel(const float* __restrict__ x, const float* __restrict__ w,
                          float* __restrict__ y)
{
    int r = blockIdx.x, tid = threadIdx.x;   // 256 threads
    const float* xr = x + (size_t)r*ED;
    float4 v = *(const float4*)(xr + tid*4);
    float s = v.x + v.y + v.z + v.w;
    float q = v.x*v.x + v.y*v.y + v.z*v.z + v.w*v.w;
    __shared__ float sm[8];
    s = blockReduceSum(s, sm);
    q = blockReduceSum(q, sm);
    float mean = s * (1.f/ED);
    float var  = q * (1.f/ED) - mean*mean;
    float rstd = rsqrtf(var + 1e-5f);
    float4 wv = *(const float4*)(w + tid*4);
    float4 o;
    o.x = (v.x - mean)*rstd*wv.x; o.y = (v.y - mean)*rstd*wv.y;
    o.z = (v.z - mean)*rstd*wv.z; o.w = (v.w - mean)*rstd*wv.w;
    *(float4*)(y + (size_t)r*ED + tid*4) = o;
}

// ---------------- causal depthwise conv (K=4) + SiLU, float4 per thread ----------------
__global__ void conv_silu_kernel(const float* __restrict__ up, const float* __restrict__ cw,
                                 const float* __restrict__ cb, float* __restrict__ xca)
{
    int idx = blockIdx.x*256 + threadIdx.x;   // < TCNT*INNER/4
    int c4 = (idx & (INNER/4 - 1)) * 4;
    int t  = idx >> 9;
    int s  = t & (SEQ-1);
    float4 acc = *(const float4*)(cb + c4);
    #pragma unroll
    for (int kk = 0; kk < 4; kk++) {
        int ss = s - 3 + kk;
        if (ss >= 0) {
            float4 uv = *(const float4*)(up + (size_t)(t - 3 + kk)*UP2 + c4);
            acc.x = fmaf(uv.x, cw[(c4+0)*4 + kk], acc.x);
            acc.y = fmaf(uv.y, cw[(c4+1)*4 + kk], acc.y);
            acc.z = fmaf(uv.z, cw[(c4+2)*4 + kk], acc.z);
            acc.w = fmaf(uv.w, cw[(c4+3)*4 + kk], acc.w);
        }
    }
    float4 o;
    o.x = acc.x / (1.f + __expf(-acc.x));
    o.y = acc.y / (1.f + __expf(-acc.y));
    o.z = acc.z / (1.f + __expf(-acc.z));
    o.w = acc.w / (1.f + __expf(-acc.w));
    *(float4*)(xca + (size_t)t*INNER + c4) = o;
}

// ---------------- 4x4 block-diagonal q/k/v projections ----------------
__global__ void headwise_kernel(const float* __restrict__ xca, const float* __restrict__ up,
    const float* __restrict__ qw, const float* __restrict__ qb,
    const float* __restrict__ kw, const float* __restrict__ kb,
    const float* __restrict__ vw, const float* __restrict__ vb,
    float* __restrict__ q, float* __restrict__ k, float* __restrict__ v)
{
    int idx = blockIdx.x*256 + threadIdx.x;   // < TCNT*NHW
    int hb = idx & (NHW-1);
    int t  = idx >> 9;
    int co = hb*4;
    float4 xc = *(const float4*)(xca + (size_t)t*INNER + co);
    float4 xm = *(const float4*)(up  + (size_t)t*UP2   + co);
    float xcv[4] = {xc.x, xc.y, xc.z, xc.w};
    float xmv[4] = {xm.x, xm.y, xm.z, xm.w};
    const float* qwp = qw + hb*16;
    const float* kwp = kw + hb*16;
    const float* vwp = vw + hb*16;
    float qo[4], ko[4], vo[4];
    #pragma unroll
    for (int o = 0; o < 4; o++) {
        float aq = qb[co+o], ak = kb[co+o], av = vb[co+o];
        #pragma unroll
        for (int d = 0; d < 4; d++) {
            aq = fmaf(xcv[d], qwp[o*4+d], aq);
            ak = fmaf(xcv[d], kwp[o*4+d], ak);
            av = fmaf(xmv[d], vwp[o*4+d], av);
        }
        qo[o] = aq; ko[o] = ak; vo[o] = av;
    }
    *(float4*)(q + (size_t)t*INNER + co) = make_float4(qo[0],qo[1],qo[2],qo[3]);
    *(float4*)(k + (size_t)t*INNER + co) = make_float4(ko[0],ko[1],ko[2],ko[3]);
    *(float4*)(v + (size_t)t*INNER + co) = make_float4(vo[0],vo[1],vo[2],vo[3]);
}

// ---------------- gate projections: ig/fg = concat(q,k,v) @ W(6144,4), 4 tokens/block ----------------
#define GTOK 4
__global__ void gates_kernel(const float* __restrict__ q, const float* __restrict__ k,
    const float* __restrict__ v,
    const float* __restrict__ igw, const float* __restrict__ igb,
    const float* __restrict__ fgw, const float* __restrict__ fgb,
    float* __restrict__ igo, float* __restrict__ fgo)
{
    int t0 = blockIdx.x * GTOK, tid = threadIdx.x;
    float li[GTOK][4], lf[GTOK][4];
    #pragma unroll
    for (int g = 0; g < GTOK; g++)
        #pragma unroll
        for (int n = 0; n < 4; n++) { li[g][n] = 0.f; lf[g][n] = 0.f; }
    for (int c = tid; c < 3*INNER; c += 256) {
        int cc = c & (INNER-1);
        const float* src = (c < INNER) ? q : (c < 2*INNER) ? k : v;
        float4 wi = *(const float4*)(igw + c*4);
        float4 wf = *(const float4*)(fgw + c*4);
        #pragma unroll
        for (int g = 0; g < GTOK; g++) {
            float xv = src[(size_t)(t0 + g)*INNER + cc];
            li[g][0] = fmaf(xv, wi.x, li[g][0]); li[g][1] = fmaf(xv, wi.y, li[g][1]);
            li[g][2] = fmaf(xv, wi.z, li[g][2]); li[g][3] = fmaf(xv, wi.w, li[g][3]);
            lf[g][0] = fmaf(xv, wf.x, lf[g][0]); lf[g][1] = fmaf(xv, wf.y, lf[g][1]);
            lf[g][2] = fmaf(xv, wf.z, lf[g][2]); lf[g][3] = fmaf(xv, wf.w, lf[g][3]);
        }
    }
    __shared__ float red[256*8];
    for (int g = 0; g < GTOK; g++) {
        __syncthreads();
        #pragma unroll
        for (int n = 0; n < 4; n++) { red[tid*8+n] = li[g][n]; red[tid*8+4+n] = lf[g][n]; }
        __syncthreads();
        for (int off = 128; off >= 1; off >>= 1) {
            if (tid < off)
                #pragma unroll
                for (int n = 0; n < 8; n++) red[tid*8+n] += red[(tid+off)*8+n];
            __syncthreads();
        }
        if (tid < 4) {
            int t = t0 + g;
            int b = t >> 11, s = t & (SEQ-1);
            igo[(b*NH + tid)*SEQ + s] = red[tid]   + igb[tid];
            fgo[(b*NH + tid)*SEQ + s] = red[4+tid] + fgb[tid];
        }
    }
}

// ---------------- per-head scans: cum = cumsum(logsigmoid(fg)), m = cum + runmax(ig - cum) ----------------
__global__ void scan_kernel(const float* __restrict__ fgv, const float* __restrict__ igv,
                            float* __restrict__ cumv, float* __restrict__ mvv)
{
    int z = blockIdx.x, tid = threadIdx.x;   // 256 threads
    __shared__ float sc[SEQ];
    __shared__ float sa[SEQ];
    __shared__ float aux[256];
    const float* fg = fgv + z*SEQ;
    const float* ig = igv + z*SEQ;
    for (int s = tid; s < SEQ; s += 256) {
        float xx = fg[s];
        sc[s] = (xx >= 0.f) ? -log1pf(expf(-xx)) : (xx - log1pf(expf(xx)));
    }
    __syncthreads();
    { // inclusive sum scan
        float vloc[8]; float run = 0.f; int base = tid*8;
        #pragma unroll
        for (int i = 0; i < 8; i++) { run += sc[base+i]; vloc[i] = run; }
        aux[tid] = run;
        __syncthreads();
        for (int off = 1; off < 256; off <<= 1) {
            float add = (tid >= off) ? aux[tid-off] : 0.f;
            __syncthreads();
            aux[tid] += add;
            __syncthreads();
        }
        float pre = (tid > 0) ? aux[tid-1] : 0.f;
        #pragma unroll
        for (int i = 0; i < 8; i++) sc[base+i] = vloc[i] + pre;
    }
    __syncthreads();
    for (int s = tid; s < SEQ; s += 256) sa[s] = ig[s] - sc[s];
    __syncthreads();
    { // inclusive max scan
        float vloc[8]; float run = -INFINITY; int base = tid*8;
        #pragma unroll
        for (int i = 0; i < 8; i++) { run = fmaxf(run, sa[base+i]); vloc[i] = run; }
        aux[tid] = run;
        __syncthreads();
        for (int off = 1; off < 256; off <<= 1) {
            float add = (tid >= off) ? aux[tid-off] : -INFINITY;
            __syncthreads();
            aux[tid] = fmaxf(aux[tid], add);
            __syncthreads();
        }
        float pre = (tid > 0) ? aux[tid-1] : -INFINITY;
        #pragma unroll
        for (int i = 0; i < 8; i++) sa[base+i] = fmaxf(vloc[i], pre);
    }
    __syncthreads();
    for (int s = tid; s < SEQ; s += 256) {
        cumv[z*SEQ + s] = sc[s];
        mvv [z*SEQ + s] = sc[s] + sa[s];
    }
}

// ---------------- masked row-sum of C -> 1/(max(|sum|, exp(-m)) + eps) ----------------
__global__ void rowsum_kernel(const float* __restrict__ Cm, const float* __restrict__ mvv,
                              float* __restrict__ invn)
{
    int row = blockIdx.x;                    // z*SEQ + i, contiguous with Cm layout
    int i = row & (SEQ-1);
    const float* cr = Cm + (size_t)row*SEQ;
    float s = 0.f;
    for (int j = threadIdx.x; j <= i; j += 256) s += cr[j];
    __shared__ float sm[8];
    s = blockReduceSum(s, sm);
    if (threadIdx.x == 0) {
        float m   = mvv[row];
        float nrm = fmaxf(fabsf(s), expf(-m));
        invn[row] = 1.f / (nrm + 1e-6f);
    }
}

// ---------------- head-norm + skip + output gate ----------------
__global__ void headnorm_gate_kernel(const float* __restrict__ hb_, const float* __restrict__ ow,
    const float* __restrict__ skipv, const float* __restrict__ xca,
    const float* __restrict__ up, float* __restrict__ g)
{
    int idx = blockIdx.x;                    // t*NH + h
    int h = idx & 3, t = idx >> 2;
    int b = t >> 11, s = t & (SEQ-1);
    const float* hr = hb_ + ((size_t)(b*NH + h)*SEQ + s)*DH;
    int tid = threadIdx.x;                   // 128 threads * 4 = 512
    float4 hv = *(const float4*)(hr + tid*4);
    float sum = hv.x + hv.y + hv.z + hv.w;
    float sq  = hv.x*hv.x + hv.y*hv.y + hv.z*hv.z + hv.w*hv.w;
    __shared__ float sm[4];
    sum = blockReduceSum(sum, sm);
    sq  = blockReduceSum(sq, sm);
    float mean = sum * (1.f/DH);
    float var  = sq * (1.f/DH) - mean*mean;
    float rstd = rsqrtf(var + 1e-5f);
    int c = h*DH + tid*4;
    float4 owv = *(const float4*)(ow + c);
    float4 sk  = *(const float4*)(skipv + c);
    float4 xc  = *(const float4*)(xca + (size_t)t*INNER + c);
    float4 zv  = *(const float4*)(up + (size_t)t*UP2 + INNER + c);
    float4 o;
    o.x = ((hv.x-mean)*rstd*owv.x + sk.x*xc.x) * (zv.x / (1.f + __expf(-zv.x)));
    o.y = ((hv.y-mean)*rstd*owv.y + sk.y*xc.y) * (zv.y / (1.f + __expf(-zv.y)));
    o.z = ((hv.z-mean)*rstd*owv.z + sk.z*xc.z) * (zv.z / (1.f + __expf(-zv.z)));
    o.w = ((hv.w-mean)*rstd*owv.w + sk.w*xc.w) * (zv.w / (1.f + __expf(-zv.w)));
    *(float4*)(g + (size_t)t*INNER + c) = o;
}

// ---------------- launch ----------------
extern "C" void kernel_launch(void* const* d_in, const int* in_sizes, int n_in,
                              void* d_out, int out_size)
{
    const float* x      = (const float*)d_in[0];
    const float* w_in   = (const float*)d_in[1];
    const float* b_in   = (const float*)d_in[2];
    const float* ln1_w  = (const float*)d_in[3];
    const float* w_up   = (const float*)d_in[4];
    const float* b_up   = (const float*)d_in[5];
    const float* conv_w = (const float*)d_in[6];
    const float* conv_b = (const float*)d_in[7];
    const float* q_w    = (const float*)d_in[8];
    const float* q_b    = (const float*)d_in[9];
    const float* k_w    = (const float*)d_in[10];
    const float* k_b    = (const float*)d_in[11];
    const float* v_w    = (const float*)d_in[12];
    const float* v_b    = (const float*)d_in[13];
    const float* ig_w   = (const float*)d_in[14];
    const float* ig_b   = (const float*)d_in[15];
    const float* fg_w   = (const float*)d_in[16];
    const float* fg_b   = (const float*)d_in[17];
    const float* onorm_w= (const float*)d_in[18];
    const float* skipv  = (const float*)d_in[19];
    const float* w_down = (const float*)d_in[20];
    const float* b_down = (const float*)d_in[21];
    const float* post_w = (const float*)d_in[22];

    static float *p_hin=nullptr,*p_xn,*p_up,*p_xca,*p_q,*p_k,*p_v,*p_ig,*p_fg,
                 *p_cum,*p_m,*p_in2,*p_C,*p_h,*p_g,*p_yt;
    if (!p_hin) {
        cudaGetSymbolAddress((void**)&p_hin, g_hin);
        cudaGetSymbolAddress((void**)&p_xn , g_xn );
        cudaGetSymbolAddress((void**)&p_up , g_up );
        cudaGetSymbolAddress((void**)&p_xca, g_xca);
        cudaGetSymbolAddress((void**)&p_q  , g_q  );
        cudaGetSymbolAddress((void**)&p_k  , g_k  );
        cudaGetSymbolAddress((void**)&p_v  , g_v  );
        cudaGetSymbolAddress((void**)&p_ig , g_ig );
        cudaGetSymbolAddress((void**)&p_fg , g_fg );
        cudaGetSymbolAddress((void**)&p_cum, g_cum);
        cudaGetSymbolAddress((void**)&p_m  , g_m  );
        cudaGetSymbolAddress((void**)&p_in2, g_in2);
        cudaGetSymbolAddress((void**)&p_C  , g_C  );
        cudaGetSymbolAddress((void**)&p_h  , g_h  );
        cudaGetSymbolAddress((void**)&p_g  , g_g  );
        cudaGetSymbolAddress((void**)&p_yt , g_yt );
    }

    // 1) h_in = x @ w_in + b_in
    sgemm<0><<<dim3(ED/128, TCNT/128, 1), 256>>>(x, w_in, p_hin, TCNT, ED, IND,
        IND, ED, ED, b_in, nullptr, nullptr, nullptr, nullptr, nullptr);
    // 2) xn = LN(h_in)*ln1_w
    ln_kernel<<<TCNT, 256>>>(p_hin, ln1_w, p_xn);
    // 3) up = xn @ w_up + b_up
    sgemm<0><<<dim3(UP2/128, TCNT/128, 1), 256>>>(p_xn, w_up, p_up, TCNT, UP2, ED,
        ED, UP2, UP2, b_up, nullptr, nullptr, nullptr, nullptr, nullptr);
    // 4) causal conv + SiLU
    conv_silu_kernel<<<(TCNT*INNER/4)/256, 256>>>(p_up, conv_w, conv_b, p_xca);
    // 5) block-diagonal q/k/v
    headwise_kernel<<<(TCNT*NHW)/256, 256>>>(p_xca, p_up, q_w, q_b, k_w, k_b, v_w, v_b,
                                             p_q, p_k, p_v);
    // 6) gates
    gates_kernel<<<TCNT/GTOK, 256>>>(p_q, p_k, p_v, ig_w, ig_b, fg_w, fg_b, p_ig, p_fg);
    // 7) per-head scans (cum, m)
    scan_kernel<<<ZB, 256>>>(p_fg, p_ig, p_cum, p_m);
    // 8) C = (q@k^T/sqrt(DH)) * decay, causal
    sgemm<2><<<dim3(SEQ/128, SEQ/128, ZB), 256>>>(p_q, p_k, p_C, SEQ, SEQ, DH,
        INNER, INNER, SEQ, nullptr, nullptr, p_cum, p_ig, p_m, nullptr);
    // 9) row normalizer
    rowsum_kernel<<<ZB*SEQ, 256>>>(p_C, p_m, p_in2);
    // 10) h = diag(invn) * C @ v
    sgemm<3><<<dim3(DH/128, SEQ/128, ZB), 256>>>(p_C, p_v, p_h, SEQ, DH, SEQ,
        SEQ, INNER, DH, nullptr, nullptr, nullptr, nullptr, nullptr, p_in2);
    // 11) head-norm + skip + output gate
    headnorm_gate_kernel<<<TCNT*NH, 128>>>(p_h, onorm_w, skipv, p_xca, p_up, p_g);
    // 12) yt = g @ w_down + b_down + h_in
    sgemm<1><<<dim3(ED/128, TCNT/128, 1), 256>>>(p_g, w_down, p_yt, TCNT, ED, INNER,
        INNER, ED, ED, b_down, p_hin, nullptr, nullptr, nullptr, nullptr);
    // 13) out = LN(yt)*post_w
    ln_kernel<<<TCNT, 256>>>(p_yt, post_w, (float*)d_out);
}

// round 13
// speedup vs baseline: 2.0898x; 1.9350x over previous
#include <cuda_runtime.h>
#include <cuda_bf16.h>
#include <stdint.h>
#include <math.h>

// ---------------- fixed problem dims ----------------
#define BATCH 2
#define SEQ   2048
#define TCNT  4096        // BATCH*SEQ
#define IND   512
#define ED    1024
#define INNER 2048
#define UP2   4096        // 2*INNER
#define NH    4
#define DH    512
#define NHW   512
#define ZB    8           // BATCH*NH

// ---------------- scratch (bss, no allocation) ----------------
__device__ float g_hin[TCNT*ED];
__device__ float g_up [(size_t)TCNT*UP2];
__device__ float g_xca[TCNT*INNER];
__device__ float g_q  [TCNT*INNER];
__device__ float g_k  [TCNT*INNER];
__device__ float g_v  [TCNT*INNER];
__device__ float g_ig [ZB*SEQ];
__device__ float g_fg [ZB*SEQ];
__device__ float g_cum[ZB*SEQ];
__device__ float g_m  [ZB*SEQ];
__device__ float g_in2[ZB*SEQ];
__device__ float g_h  [(size_t)ZB*SEQ*DH];
__device__ float g_yt [TCNT*ED];

// bf16 split operands
__device__ __nv_bfloat16 g_xh [TCNT*IND],  g_xl [TCNT*IND];
__device__ __nv_bfloat16 g_wiTh[ED*IND],   g_wiTl[ED*IND];
__device__ __nv_bfloat16 g_lnh[TCNT*ED],   g_lnl[TCNT*ED];
__device__ __nv_bfloat16 g_wupTh[(size_t)UP2*ED], g_wupTl[(size_t)UP2*ED];
__device__ __nv_bfloat16 g_qh [TCNT*INNER], g_ql [TCNT*INNER];
__device__ __nv_bfloat16 g_kh [TCNT*INNER], g_kl [TCNT*INNER];
__device__ __nv_bfloat16 g_vTh[(size_t)ZB*DH*SEQ], g_vTl[(size_t)ZB*DH*SEQ];
__device__ __nv_bfloat16 g_Ch [(size_t)ZB*SEQ*SEQ], g_Cl [(size_t)ZB*SEQ*SEQ];
__device__ __nv_bfloat16 g_gh [TCNT*INNER], g_gl [TCNT*INNER];
__device__ __nv_bfloat16 g_wdTh[(size_t)ED*INNER], g_wdTl[(size_t)ED*INNER];

// ---------------- PTX helpers (mma.sync / ldmatrix / cp.async; all plain sm_80+ PTX) ----------------
__device__ __forceinline__ uint32_t smem_u32(const void* p) {
    uint32_t a;
    asm("{ .reg .u64 t; cvta.to.shared.u64 t, %1; cvt.u32.u64 %0, t; }" : "=r"(a) : "l"(p));
    return a;
}

#define LDSM_X4(r0,r1,r2,r3,addr) \
    asm volatile("ldmatrix.sync.aligned.m8n8.x4.shared.b16 {%0,%1,%2,%3}, [%4];" \
        : "=r"(r0), "=r"(r1), "=r"(r2), "=r"(r3) : "r"(addr))

#define CP16(dst,src) \
    asm volatile("cp.async.cg.shared.global [%0], [%1], 16;" :: "r"(dst), "l"(src))
#define CP_COMMIT() asm volatile("cp.async.commit_group;" ::: "memory")

__device__ __forceinline__ void mma_bf16(float* d, const uint32_t* a, const uint32_t* b) {
    asm volatile("mma.sync.aligned.m16n8k16.row.col.f32.bf16.bf16.f32 "
        "{%0,%1,%2,%3}, {%4,%5,%6,%7}, {%8,%9}, {%0,%1,%2,%3};"
        : "+f"(d[0]), "+f"(d[1]), "+f"(d[2]), "+f"(d[3])
        : "r"(a[0]), "r"(a[1]), "r"(a[2]), "r"(a[3]), "r"(b[0]), "r"(b[1]));
}

__device__ __forceinline__ void bf_split(float x, __nv_bfloat16& hi, __nv_bfloat16& lo) {
    hi = __float2bfloat16_rn(x);
    lo = __float2bfloat16_rn(x - __bfloat162float(hi));
}

// ---------------- HMMA GEMM: 128x128 tile, K-chunks of 32 (hi|lo packed 128B rows) ----------------
// smem row r (of A or B tile): [hi k0..k31 (64B) | lo k0..k31 (64B)], 16B-column XOR swizzle by (r&7).
// 8 warps: warp tile 64x32 (wm = wid&1 over M, wn = wid>>2... wn = wid>>1 over N).
// EPI 0: Cf = A@B + bias[n]
// EPI 1: Cf = A@B + bias[n] + addm[m,n]
// EPI 2: per-head qk -> (A@B^T/sqrt(DH)) * exp(cum_i - cum_j + ig_j - m_i), j<=i else 0 -> Coh/Col split
// EPI 3: per-head C@v, k-limit m0+128, row-scaled by invn[i] -> Cf
#define KB 32
#define TILE_BYTES 16384   // 128 rows * 128B

template<int EPI>
__global__ void __launch_bounds__(256)
mma_gemm(const __nv_bfloat16* __restrict__ Ah, const __nv_bfloat16* __restrict__ Al,
         const __nv_bfloat16* __restrict__ Bh, const __nv_bfloat16* __restrict__ Bl,
         float* __restrict__ Cf, __nv_bfloat16* __restrict__ Coh, __nv_bfloat16* __restrict__ Col,
         int K, int lda, int ldb, int ldc,
         const float* __restrict__ bias, const float* __restrict__ addm,
         const float* __restrict__ cumv, const float* __restrict__ igv,
         const float* __restrict__ mvv,  const float* __restrict__ invn)
{
    const int m0 = blockIdx.y * 128;
    const int n0 = blockIdx.x * 128;
    if (EPI == 2 && n0 > m0) return;
    const int z = blockIdx.z;

    if (EPI == 2) {
        int b = z >> 2, h = z & 3;
        size_t o = ((size_t)b * SEQ) * INNER + (size_t)h * DH;
        Ah += o; Al += o; Bh += o; Bl += o;
    } else if (EPI == 3) {
        size_t ao = (size_t)z * SEQ * SEQ;
        size_t bo = (size_t)z * DH * SEQ;
        Ah += ao; Al += ao; Bh += bo; Bl += bo;
        Cf += (size_t)z * SEQ * DH;
    }
    const int kend = (EPI == 3) ? (m0 + 128) : K;
    const int NC = kend / KB;

    extern __shared__ __align__(1024) char smem[];
    const uint32_t smemb = smem_u32(smem);
    // layout: sA[0] sA[1] sB[0] sB[1], each TILE_BYTES

    const int tid  = threadIdx.x;
    const int lane = tid & 31, wid = tid >> 5;
    const int wm = wid & 1, wn = wid >> 1;
    const int rr = lane & 7, q = lane >> 3;
    const int g  = lane >> 2, t = lane & 3;

    float acc[4][4][4];
    #pragma unroll
    for (int i = 0; i < 4; i++)
        #pragma unroll
        for (int j = 0; j < 4; j++)
            #pragma unroll
            for (int e = 0; e < 4; e++) acc[i][j][e] = 0.f;

    auto issue = [&](int c) {
        const int bsel = c & 1;
        const int k0 = c * KB;
        const uint32_t dA = smemb + bsel * TILE_BYTES;
        const uint32_t dB = smemb + 2 * TILE_BYTES + bsel * TILE_BYTES;
        #pragma unroll
        for (int it = 0; it < 8; it++) {
            int u = it * 256 + tid;          // 0..2047 (1024 16B-chunks per tile)
            int tile = u >> 10;
            int uu = u & 1023;
            int r = uu >> 3, col = uu & 7;   // col 0..3 hi, 4..7 lo
            const __nv_bfloat16* src;
            if (tile == 0) src = ((col < 4) ? Ah : Al) + (size_t)(m0 + r) * lda + k0 + (col & 3) * 8;
            else           src = ((col < 4) ? Bh : Bl) + (size_t)(n0 + r) * ldb + k0 + (col & 3) * 8;
            uint32_t dst = (tile ? dB : dA) + r * 128 + ((col ^ (r & 7)) << 4);
            CP16(dst, (const void*)src);
        }
        CP_COMMIT();
    };

    issue(0);
    for (int c = 0; c < NC; c++) {
        if (c + 1 < NC) {
            issue(c + 1);
            asm volatile("cp.async.wait_group 1;" ::: "memory");
        } else {
            asm volatile("cp.async.wait_group 0;" ::: "memory");
        }
        __syncthreads();
        const int bsel = c & 1;
        const uint32_t baseA = smemb + bsel * TILE_BYTES;
        const uint32_t baseB = smemb + 2 * TILE_BYTES + bsel * TILE_BYTES;
        #pragma unroll
        for (int khalf = 0; khalf < 2; khalf++) {
            const int kch = 2 * khalf;       // hi 16B cols
            const int kcl = 4 + 2 * khalf;   // lo 16B cols
            // B fragments: x4 covers two n8 tiles. lane: row = nb + rr + (q>>1)*8, kc += (q&1)
            uint32_t Bh_[4][2], Bl_[4][2];
            #pragma unroll
            for (int p = 0; p < 2; p++) {
                int rB = wn * 32 + p * 16 + rr + (q >> 1) * 8;
                uint32_t ah = baseB + rB * 128 + (((kch + (q & 1)) ^ (rB & 7)) << 4);
                LDSM_X4(Bh_[2*p][0], Bh_[2*p][1], Bh_[2*p+1][0], Bh_[2*p+1][1], ah);
                uint32_t al = baseB + rB * 128 + (((kcl + (q & 1)) ^ (rB & 7)) << 4);
                LDSM_X4(Bl_[2*p][0], Bl_[2*p][1], Bl_[2*p+1][0], Bl_[2*p+1][1], al);
            }
            // A hi fragments. lane: row = mb + rr + (q&1)*8, kc += (q>>1)
            uint32_t Af[4][4];
            #pragma unroll
            for (int mi = 0; mi < 4; mi++) {
                int rA = wm * 64 + mi * 16 + rr + (q & 1) * 8;
                uint32_t aa = baseA + rA * 128 + (((kch + (q >> 1)) ^ (rA & 7)) << 4);
                LDSM_X4(Af[mi][0], Af[mi][1], Af[mi][2], Af[mi][3], aa);
            }
            #pragma unroll
            for (int mi = 0; mi < 4; mi++)
                #pragma unroll
                for (int ni = 0; ni < 4; ni++) {
                    mma_bf16(acc[mi][ni], Af[mi], Bh_[ni]);   // hi*hi
                    mma_bf16(acc[mi][ni], Af[mi], Bl_[ni]);   // hi*lo
                }
            // A lo fragments (reuse regs)
            #pragma unroll
            for (int mi = 0; mi < 4; mi++) {
                int rA = wm * 64 + mi * 16 + rr + (q & 1) * 8;
                uint32_t aa = baseA + rA * 128 + (((kcl + (q >> 1)) ^ (rA & 7)) << 4);
                LDSM_X4(Af[mi][0], Af[mi][1], Af[mi][2], Af[mi][3], aa);
            }
            #pragma unroll
            for (int mi = 0; mi < 4; mi++)
                #pragma unroll
                for (int ni = 0; ni < 4; ni++)
                    mma_bf16(acc[mi][ni], Af[mi], Bh_[ni]);   // lo*hi
        }
        __syncthreads();
    }

    // ---------------- epilogue: fragment layout D[m = .. + g + 8h][n = .. + 2t (+1)] ----------------
    const float SC = 0.04419417382415922f; // 1/sqrt(512)
    #pragma unroll
    for (int mi = 0; mi < 4; mi++)
        #pragma unroll
        for (int h = 0; h < 2; h++) {
            int m = m0 + wm * 64 + mi * 16 + g + 8 * h;
            if (EPI == 0 || EPI == 1) {
                #pragma unroll
                for (int ni = 0; ni < 4; ni++) {
                    int n = n0 + wn * 32 + ni * 8 + 2 * t;
                    float2 o;
                    o.x = acc[mi][ni][2*h+0] + bias[n];
                    o.y = acc[mi][ni][2*h+1] + bias[n+1];
                    if (EPI == 1) {
                        float2 ad = *(const float2*)(addm + (size_t)m*ldc + n);
                        o.x += ad.x; o.y += ad.y;
                    }
                    *(float2*)(Cf + (size_t)m*ldc + n) = o;
                }
            } else if (EPI == 2) {
                const float* cu = cumv + z*SEQ;
                const float* ip = igv  + z*SEQ;
                float ci = cu[m], mim = mvv[z*SEQ + m];
                size_t base = (size_t)z*SEQ*SEQ + (size_t)m*SEQ;
                #pragma unroll
                for (int ni = 0; ni < 4; ni++) {
                    int n = n0 + wn * 32 + ni * 8 + 2 * t;
                    float v0 = (n+0 <= m) ? acc[mi][ni][2*h+0]*SC*__expf(ci - cu[n+0] + ip[n+0] - mim) : 0.f;
                    float v1 = (n+1 <= m) ? acc[mi][ni][2*h+1]*SC*__expf(ci - cu[n+1] + ip[n+1] - mim) : 0.f;
                    __nv_bfloat16 h0, l0, h1, l1;
                    bf_split(v0, h0, l0); bf_split(v1, h1, l1);
                    __nv_bfloat162 hh; hh.x = h0; hh.y = h1;
                    __nv_bfloat162 ll; ll.x = l0; ll.y = l1;
                    *(__nv_bfloat162*)(Coh + base + n) = hh;
                    *(__nv_bfloat162*)(Col + base + n) = ll;
                }
            } else { // EPI 3
                float s = invn[z*SEQ + m];
                #pragma unroll
                for (int ni = 0; ni < 4; ni++) {
                    int n = n0 + wn * 32 + ni * 8 + 2 * t;
                    float2 o;
                    o.x = acc[mi][ni][2*h+0] * s;
                    o.y = acc[mi][ni][2*h+1] * s;
                    *(float2*)(Cf + (size_t)m*ldc + n) = o;
                }
            }
        }
}

// ---------------- helpers ----------------
__device__ __forceinline__ float blockReduceSum(float v, float* sm) {
    int tid = threadIdx.x;
    __syncthreads();
    #pragma unroll
    for (int o = 16; o > 0; o >>= 1) v += __shfl_down_sync(0xffffffffu, v, o);
    if ((tid & 31) == 0) sm[tid >> 5] = v;
    __syncthreads();
    int nw = blockDim.x >> 5;
    float r = (tid < nw) ? sm[tid] : 0.f;
    if (tid < 32) {
        #pragma unroll
        for (int o = 16; o > 0; o >>= 1) r += __shfl_down_sync(0xffffffffu, r, o);
        if (tid == 0) sm[0] = r;
    }
    __syncthreads();
    return sm[0];
}

// ---------------- elementwise split: x -> hi/lo bf16 ----------------
__global__ void split_kernel(const float* __restrict__ x,
                             __nv_bfloat16* __restrict__ hi, __nv_bfloat16* __restrict__ lo, int n4)
{
    int i = blockIdx.x*256 + threadIdx.x;
    if (i >= n4) return;
    float4 v = *(const float4*)(x + i*4);
    __nv_bfloat16 h0,l0,h1,l1,h2,l2,h3,l3;
    bf_split(v.x,h0,l0); bf_split(v.y,h1,l1); bf_split(v.z,h2,l2); bf_split(v.w,h3,l3);
    __nv_bfloat162 a,b; a.x=h0;a.y=h1; b.x=h2;b.y=h3;
    *(__nv_bfloat162*)(hi + i*4) = a; *(__nv_bfloat162*)(hi + i*4 + 2) = b;
    a.x=l0;a.y=l1; b.x=l2;b.y=l3;
    *(__nv_bfloat162*)(lo + i*4) = a; *(__nv_bfloat162*)(lo + i*4 + 2) = b;
}

// ---------------- transpose + split: W [R,Cc] f32 -> Wt hi/lo [Cc,R] bf16 ----------------
__global__ void tsplit_kernel(const float* __restrict__ W,
                              __nv_bfloat16* __restrict__ Th, __nv_bfloat16* __restrict__ Tl,
                              int R, int Cc)
{
    __shared__ float tile[32][33];
    int r0 = blockIdx.y*32, c0 = blockIdx.x*32;
    int tx = threadIdx.x & 31, ty = threadIdx.x >> 5;   // 256 threads
    for (int i = ty; i < 32; i += 8)
        tile[i][tx] = W[(size_t)(r0+i)*Cc + c0 + tx];
    __syncthreads();
    for (int i = ty; i < 32; i += 8) {
        float v = tile[tx][i];           // = W[r0+tx][c0+i]
        __nv_bfloat16 h, l; bf_split(v, h, l);
        size_t o = (size_t)(c0+i)*R + r0 + tx;
        Th[o] = h; Tl[o] = l;
    }
}

// ---------------- per-head v transpose + split: v[T,INNER] -> vT[z][n][j] ----------------
__global__ void vtrans_kernel(const float* __restrict__ v,
                              __nv_bfloat16* __restrict__ Th, __nv_bfloat16* __restrict__ Tl)
{
    int z = blockIdx.z; int b = z >> 2, h = z & 3;
    int j0 = blockIdx.x*32, n0 = blockIdx.y*32;
    __shared__ float tile[32][33];
    int tx = threadIdx.x & 31, ty = threadIdx.x >> 5;
    for (int i = ty; i < 32; i += 8)
        tile[i][tx] = v[(size_t)(b*SEQ + j0 + i)*INNER + h*DH + n0 + tx];
    __syncthreads();
    for (int i = ty; i < 32; i += 8) {
        float val = tile[tx][i];         // v[j0+tx][n0+i]
        __nv_bfloat16 hh, ll; bf_split(val, hh, ll);
        size_t o = (size_t)z*DH*SEQ + (size_t)(n0+i)*SEQ + j0 + tx;
        Th[o] = hh; Tl[o] = ll;
    }
}

// ---------------- LayerNorm -> bf16 hi/lo split (width 1024) ----------------
__global__ void ln_split_kernel(const float* __restrict__ x, const float* __restrict__ w,
                                __nv_bfloat16* __restrict__ yh, __nv_bfloat16* __restrict__ yl)
{
    int r = blockIdx.x, tid = threadIdx.x;   // 256 threads
    const float* xr = x + (size_t)r*ED;
    float4 v = *(const float4*)(xr + tid*4);
    float s = v.x + v.y + v.z + v.w;
    float q = v.x*v.x + v.y*v.y + v.z*v.z + v.w*v.w;
    __shared__ float sm[8];
    s = blockReduceSum(s, sm);
    q = blockReduceSum(q, sm);
    float mean = s * (1.f/ED);
    float var  = q * (1.f/ED) - mean*mean;
    float rstd = rsqrtf(var + 1e-5f);
    float4 wv = *(const float4*)(w + tid*4);
    float o0 = (v.x - mean)*rstd*wv.x, o1 = (v.y - mean)*rstd*wv.y;
    float o2 = (v.z - mean)*rstd*wv.z, o3 = (v.w - mean)*rstd*wv.w;
    __nv_bfloat16 h0,l0,h1,l1,h2,l2,h3,l3;
    bf_split(o0,h0,l0); bf_split(o1,h1,l1); bf_split(o2,h2,l2); bf_split(o3,h3,l3);
    size_t base = (size_t)r*ED + tid*4;
    __nv_bfloat162 a; a.x=h0;a.y=h1; *(__nv_bfloat162*)(yh+base)=a;
    a.x=h2;a.y=h3; *(__nv_bfloat162*)(yh+base+2)=a;
    a.x=l0;a.y=l1; *(__nv_bfloat162*)(yl+base)=a;
    a.x=l2;a.y=l3; *(__nv_bfloat162*)(yl+base+2)=a;
}

// ---------------- plain f32 LayerNorm (final output) ----------------
__global__ void ln_kernel(const float* __restrict__ x, const float* __restrict__ w,
                          float* __restrict__ y)
{
    int r = blockIdx.x, tid = threadIdx.x;
    const float* xr = x + (size_t)r*ED;
    float4 v = *(const float4*)(xr + tid*4);
    float s = v.x + v.y + v.z + v.w;
    float q = v.x*v.x + v.y*v.y + v.z*v.z + v.w*v.w;
    __shared__ float sm[8];
    s = blockReduceSum(s, sm);
    q = blockReduceSum(q, sm);
    float mean = s * (1.f/ED);
    float var  = q * (1.f/ED) - mean*mean;
    float rstd = rsqrtf(var + 1e-5f);
    float4 wv = *(const float4*)(w + tid*4);
    float4 o;
    o.x = (v.x - mean)*rstd*wv.x; o.y = (v.y - mean)*rstd*wv.y;
    o.z = (v.z - mean)*rstd*wv.z; o.w = (v.w - mean)*rstd*wv.w;
    *(float4*)(y + (size_t)r*ED + tid*4) = o;
}

// ---------------- causal depthwise conv (K=4) + SiLU ----------------
__global__ void conv_silu_kernel(const float* __restrict__ up, const float* __restrict__ cw,
                                 const float* __restrict__ cb, float* __restrict__ xca)
{
    int idx = blockIdx.x*256 + threadIdx.x;   // < TCNT*INNER
    int c = idx & (INNER-1);
    int t = idx >> 11;
    int s = t & (SEQ-1);
    float acc = cb[c];
    const float* w = cw + c*4;
    #pragma unroll
    for (int kk = 0; kk < 4; kk++) {
        int ss = s - 3 + kk;
        if (ss >= 0) acc = fmaf(up[(size_t)(t - 3 + kk)*UP2 + c], w[kk], acc);
    }
    xca[idx] = acc / (1.f + __expf(-acc));
}

// ---------------- 4x4 block-diagonal q/k/v projections (+ bf16 splits of q,k) ----------------
__global__ void headwise_kernel(const float* __restrict__ xca, const float* __restrict__ up,
    const float* __restrict__ qw, const float* __restrict__ qb,
    const float* __restrict__ kw, const float* __restrict__ kb,
    const float* __restrict__ vw, const float* __restrict__ vb,
    float* __restrict__ q, float* __restrict__ k, float* __restrict__ v,
    __nv_bfloat16* __restrict__ qh, __nv_bfloat16* __restrict__ ql,
    __nv_bfloat16* __restrict__ kh, __nv_bfloat16* __restrict__ kl)
{
    int idx = blockIdx.x*256 + threadIdx.x;   // < TCNT*NHW
    int hb = idx & (NHW-1);
    int t  = idx >> 9;
    int co = hb*4;
    float4 xc = *(const float4*)(xca + (size_t)t*INNER + co);
    float4 xm = *(const float4*)(up  + (size_t)t*UP2   + co);
    float xcv[4] = {xc.x, xc.y, xc.z, xc.w};
    float xmv[4] = {xm.x, xm.y, xm.z, xm.w};
    const float* qwp = qw + hb*16;
    const float* kwp = kw + hb*16;
    const float* vwp = vw + hb*16;
    float qo[4], ko[4], vo[4];
    #pragma unroll
    for (int o = 0; o < 4; o++) {
        float aq = qb[co+o], ak = kb[co+o], av = vb[co+o];
        #pragma unroll
        for (int d = 0; d < 4; d++) {
            aq = fmaf(xcv[d], qwp[o*4+d], aq);
            ak = fmaf(xcv[d], kwp[o*4+d], ak);
            av = fmaf(xmv[d], vwp[o*4+d], av);
        }
        qo[o] = aq; ko[o] = ak; vo[o] = av;
    }
    size_t base = (size_t)t*INNER + co;
    *(float4*)(q + base) = make_float4(qo[0],qo[1],qo[2],qo[3]);
    *(float4*)(k + base) = make_float4(ko[0],ko[1],ko[2],ko[3]);
    *(float4*)(v + base) = make_float4(vo[0],vo[1],vo[2],vo[3]);
    __nv_bfloat16 h0,l0,h1,l1,h2,l2,h3,l3;
    bf_split(qo[0],h0,l0); bf_split(qo[1],h1,l1); bf_split(qo[2],h2,l2); bf_split(qo[3],h3,l3);
    __nv_bfloat162 a; a.x=h0;a.y=h1; *(__nv_bfloat162*)(qh+base)=a;
    a.x=h2;a.y=h3; *(__nv_bfloat162*)(qh+base+2)=a;
    a.x=l0;a.y=l1; *(__nv_bfloat162*)(ql+base)=a;
    a.x=l2;a.y=l3; *(__nv_bfloat162*)(ql+base+2)=a;
    bf_split(ko[0],h0,l0); bf_split(ko[1],h1,l1); bf_split(ko[2],h2,l2); bf_split(ko[3],h3,l3);
    a.x=h0;a.y=h1; *(__nv_bfloat162*)(kh+base)=a;
    a.x=h2;a.y=h3; *(__nv_bfloat162*)(kh+base+2)=a;
    a.x=l0;a.y=l1; *(__nv_bfloat162*)(kl+base)=a;
    a.x=l2;a.y=l3; *(__nv_bfloat162*)(kl+base+2)=a;
}

// ---------------- gate projections: ig/fg = concat(q,k,v) @ W(6144,4), 4 tokens/block ----------------
#define GTOK 4
__global__ void gates_kernel(const float* __restrict__ q, const float* __restrict__ k,
    const float* __restrict__ v,
    const float* __restrict__ igw, const float* __restrict__ igb,
    const float* __restrict__ fgw, const float* __restrict__ fgb,
    float* __restrict__ igo, float* __restrict__ fgo)
{
    int t0 = blockIdx.x * GTOK, tid = threadIdx.x;
    float li[GTOK][4], lf[GTOK][4];
    #pragma unroll
    for (int g = 0; g < GTOK; g++)
        #pragma unroll
        for (int n = 0; n < 4; n++) { li[g][n] = 0.f; lf[g][n] = 0.f; }
    for (int c = tid; c < 3*INNER; c += 256) {
        int cc = c & (INNER-1);
        const float* src = (c < INNER) ? q : (c < 2*INNER) ? k : v;
        float4 wi = *(const float4*)(igw + c*4);
        float4 wf = *(const float4*)(fgw + c*4);
        #pragma unroll
        for (int g = 0; g < GTOK; g++) {
            float xv = src[(size_t)(t0 + g)*INNER + cc];
            li[g][0] = fmaf(xv, wi.x, li[g][0]); li[g][1] = fmaf(xv, wi.y, li[g][1]);
            li[g][2] = fmaf(xv, wi.z, li[g][2]); li[g][3] = fmaf(xv, wi.w, li[g][3]);
            lf[g][0] = fmaf(xv, wf.x, lf[g][0]); lf[g][1] = fmaf(xv, wf.y, lf[g][1]);
            lf[g][2] = fmaf(xv, wf.z, lf[g][2]); lf[g][3] = fmaf(xv, wf.w, lf[g][3]);
        }
    }
    __shared__ float red[256*8];
    for (int g = 0; g < GTOK; g++) {
        __syncthreads();
        #pragma unroll
        for (int n = 0; n < 4; n++) { red[tid*8+n] = li[g][n]; red[tid*8+4+n] = lf[g][n]; }
        __syncthreads();
        for (int off = 128; off >= 1; off >>= 1) {
            if (tid < off)
                #pragma unroll
                for (int n = 0; n < 8; n++) red[tid*8+n] += red[(tid+off)*8+n];
            __syncthreads();
        }
        if (tid < 4) {
            int t = t0 + g;
            int b = t >> 11, s = t & (SEQ-1);
            igo[(b*NH + tid)*SEQ + s] = red[tid]   + igb[tid];
            fgo[(b*NH + tid)*SEQ + s] = red[4+tid] + fgb[tid];
        }
    }
}

// ---------------- per-head scans ----------------
__global__ void scan_kernel(const float* __restrict__ fgv, const float* __restrict__ igv,
                            float* __restrict__ cumv, float* __restrict__ mvv)
{
    int z = blockIdx.x, tid = threadIdx.x;   // 256 threads
    __shared__ float sc[SEQ];
    __shared__ float sa[SEQ];
    __shared__ float aux[256];
    const float* fg = fgv + z*SEQ;
    const float* ig = igv + z*SEQ;
    for (int s = tid; s < SEQ; s += 256) {
        float xx = fg[s];
        sc[s] = (xx >= 0.f) ? -log1pf(expf(-xx)) : (xx - log1pf(expf(xx)));
    }
    __syncthreads();
    {
        float vloc[8]; float run = 0.f; int base = tid*8;
        #pragma unroll
        for (int i = 0; i < 8; i++) { run += sc[base+i]; vloc[i] = run; }
        aux[tid] = run;
        __syncthreads();
        for (int off = 1; off < 256; off <<= 1) {
            float add = (tid >= off) ? aux[tid-off] : 0.f;
            __syncthreads();
            aux[tid] += add;
            __syncthreads();
        }
        float pre = (tid > 0) ? aux[tid-1] : 0.f;
        #pragma unroll
        for (int i = 0; i < 8; i++) sc[base+i] = vloc[i] + pre;
    }
    __syncthreads();
    for (int s = tid; s < SEQ; s += 256) sa[s] = ig[s] - sc[s];
    __syncthreads();
    {
        float vloc[8]; float run = -INFINITY; int base = tid*8;
        #pragma unroll
        for (int i = 0; i < 8; i++) { run = fmaxf(run, sa[base+i]); vloc[i] = run; }
        aux[tid] = run;
        __syncthreads();
        for (int off = 1; off < 256; off <<= 1) {
            float add = (tid >= off) ? aux[tid-off] : -INFINITY;
            __syncthreads();
            aux[tid] = fmaxf(aux[tid], add);
            __syncthreads();
        }
        float pre = (tid > 0) ? aux[tid-1] : -INFINITY;
        #pragma unroll
        for (int i = 0; i < 8; i++) sa[base+i] = fmaxf(vloc[i], pre);
    }
    __syncthreads();
    for (int s = tid; s < SEQ; s += 256) {
        cumv[z*SEQ + s] = sc[s];
        mvv [z*SEQ + s] = sc[s] + sa[s];
    }
}

// ---------------- masked row-sum of C (bf16 hi+lo) -> 1/(max(|sum|, exp(-m)) + eps) ----------------
__global__ void rowsum_kernel(const __nv_bfloat16* __restrict__ Ch, const __nv_bfloat16* __restrict__ Cl,
                              const float* __restrict__ mvv, float* __restrict__ invn)
{
    int row = blockIdx.x;                    // z*SEQ + i
    int i = row & (SEQ-1);
    const __nv_bfloat16* ch = Ch + (size_t)row*SEQ;
    const __nv_bfloat16* cl = Cl + (size_t)row*SEQ;
    float s = 0.f;
    for (int j = threadIdx.x; j <= i; j += 256)
        s += __bfloat162float(ch[j]) + __bfloat162float(cl[j]);
    __shared__ float sm[8];
    s = blockReduceSum(s, sm);
    if (threadIdx.x == 0) {
        float m   = mvv[row];
        float nrm = fmaxf(fabsf(s), expf(-m));
        invn[row] = 1.f / (nrm + 1e-6f);
    }
}

// ---------------- head-norm + skip + output gate -> bf16 hi/lo split ----------------
__global__ void headnorm_gate_kernel(const float* __restrict__ hb_, const float* __restrict__ ow,
    const float* __restrict__ skipv, const float* __restrict__ xca,
    const float* __restrict__ up,
    __nv_bfloat16* __restrict__ gh, __nv_bfloat16* __restrict__ gl)
{
    int idx = blockIdx.x;                    // t*NH + h
    int h = idx & 3, t = idx >> 2;
    int b = t >> 11, s = t & (SEQ-1);
    const float* hr = hb_ + ((size_t)(b*NH + h)*SEQ + s)*DH;
    int tid = threadIdx.x;                   // 128 threads * 4 = 512
    float4 hv = *(const float4*)(hr + tid*4);
    float sum = hv.x + hv.y + hv.z + hv.w;
    float sq  = hv.x*hv.x + hv.y*hv.y + hv.z*hv.z + hv.w*hv.w;
    __shared__ float sm[4];
    sum = blockReduceSum(sum, sm);
    sq  = blockReduceSum(sq, sm);
    float mean = sum * (1.f/DH);
    float var  = sq * (1.f/DH) - mean*mean;
    float rstd = rsqrtf(var + 1e-5f);
    int c = h*DH + tid*4;
    float4 owv = *(const float4*)(ow + c);
    float4 sk  = *(const float4*)(skipv + c);
    float4 xc  = *(const float4*)(xca + (size_t)t*INNER + c);
    float4 zv  = *(const float4*)(up + (size_t)t*UP2 + INNER + c);
    float o0 = ((hv.x-mean)*rstd*owv.x + sk.x*xc.x) * (zv.x / (1.f + __expf(-zv.x)));
    float o1 = ((hv.y-mean)*rstd*owv.y + sk.y*xc.y) * (zv.y / (1.f + __expf(-zv.y)));
    float o2 = ((hv.z-mean)*rstd*owv.z + sk.z*xc.z) * (zv.z / (1.f + __expf(-zv.z)));
    float o3 = ((hv.w-mean)*rstd*owv.w + sk.w*xc.w) * (zv.w / (1.f + __expf(-zv.w)));
    size_t base = (size_t)t*INNER + c;
    __nv_bfloat16 h0,l0,h1,l1,h2,l2,h3,l3;
    bf_split(o0,h0,l0); bf_split(o1,h1,l1); bf_split(o2,h2,l2); bf_split(o3,h3,l3);
    __nv_bfloat162 a; a.x=h0;a.y=h1; *(__nv_bfloat162*)(gh+base)=a;
    a.x=h2;a.y=h3; *(__nv_bfloat162*)(gh+base+2)=a;
    a.x=l0;a.y=l1; *(__nv_bfloat162*)(gl+base)=a;
    a.x=l2;a.y=l3; *(__nv_bfloat162*)(gl+base+2)=a;
}

// ---------------- launch ----------------
#define GEMM_SMEM (4*TILE_BYTES)   // 64 KB (2-stage double buffer, A+B)

extern "C" void kernel_launch(void* const* d_in, const int* in_sizes, int n_in,
                              void* d_out, int out_size)
{
    const float* x      = (const float*)d_in[0];
    const float* w_in   = (const float*)d_in[1];
    const float* b_in   = (const float*)d_in[2];
    const float* ln1_w  = (const float*)d_in[3];
    const float* w_up   = (const float*)d_in[4];
    const float* b_up   = (const float*)d_in[5];
    const float* conv_w = (const float*)d_in[6];
    const float* conv_b = (const float*)d_in[7];
    const float* q_w    = (const float*)d_in[8];
    const float* q_b    = (const float*)d_in[9];
    const float* k_w    = (const float*)d_in[10];
    const float* k_b    = (const float*)d_in[11];
    const float* v_w    = (const float*)d_in[12];
    const float* v_b    = (const float*)d_in[13];
    const float* ig_w   = (const float*)d_in[14];
    const float* ig_b   = (const float*)d_in[15];
    const float* fg_w   = (const float*)d_in[16];
    const float* fg_b   = (const float*)d_in[17];
    const float* onorm_w= (const float*)d_in[18];
    const float* skipv  = (const float*)d_in[19];
    const float* w_down = (const float*)d_in[20];
    const float* b_down = (const float*)d_in[21];
    const float* post_w = (const float*)d_in[22];

    static float *p_hin=nullptr,*p_up,*p_xca,*p_q,*p_k,*p_v,*p_ig,*p_fg,
                 *p_cum,*p_m,*p_in2,*p_h,*p_yt;
    static __nv_bfloat16 *p_xh,*p_xl,*p_wiTh,*p_wiTl,*p_lnh,*p_lnl,*p_wupTh,*p_wupTl,
                 *p_qh,*p_ql,*p_kh,*p_kl,*p_vTh,*p_vTl,*p_Ch,*p_Cl,*p_gh,*p_gl,*p_wdTh,*p_wdTl;
    if (!p_hin) {
        cudaGetSymbolAddress((void**)&p_hin, g_hin);
        cudaGetSymbolAddress((void**)&p_up , g_up );
        cudaGetSymbolAddress((void**)&p_xca, g_xca);
        cudaGetSymbolAddress((void**)&p_q  , g_q  );
        cudaGetSymbolAddress((void**)&p_k  , g_k  );
        cudaGetSymbolAddress((void**)&p_v  , g_v  );
        cudaGetSymbolAddress((void**)&p_ig , g_ig );
        cudaGetSymbolAddress((void**)&p_fg , g_fg );
        cudaGetSymbolAddress((void**)&p_cum, g_cum);
        cudaGetSymbolAddress((void**)&p_m  , g_m  );
        cudaGetSymbolAddress((void**)&p_in2, g_in2);
        cudaGetSymbolAddress((void**)&p_h  , g_h  );
        cudaGetSymbolAddress((void**)&p_yt , g_yt );
        cudaGetSymbolAddress((void**)&p_xh , g_xh );
        cudaGetSymbolAddress((void**)&p_xl , g_xl );
        cudaGetSymbolAddress((void**)&p_wiTh, g_wiTh);
        cudaGetSymbolAddress((void**)&p_wiTl, g_wiTl);
        cudaGetSymbolAddress((void**)&p_lnh, g_lnh);
        cudaGetSymbolAddress((void**)&p_lnl, g_lnl);
        cudaGetSymbolAddress((void**)&p_wupTh, g_wupTh);
        cudaGetSymbolAddress((void**)&p_wupTl, g_wupTl);
        cudaGetSymbolAddress((void**)&p_qh , g_qh );
        cudaGetSymbolAddress((void**)&p_ql , g_ql );
        cudaGetSymbolAddress((void**)&p_kh , g_kh );
        cudaGetSymbolAddress((void**)&p_kl , g_kl );
        cudaGetSymbolAddress((void**)&p_vTh, g_vTh);
        cudaGetSymbolAddress((void**)&p_vTl, g_vTl);
        cudaGetSymbolAddress((void**)&p_Ch , g_Ch );
        cudaGetSymbolAddress((void**)&p_Cl , g_Cl );
        cudaGetSymbolAddress((void**)&p_gh , g_gh );
        cudaGetSymbolAddress((void**)&p_gl , g_gl );
        cudaGetSymbolAddress((void**)&p_wdTh, g_wdTh);
        cudaGetSymbolAddress((void**)&p_wdTl, g_wdTl);
        cudaFuncSetAttribute(mma_gemm<0>, cudaFuncAttributeMaxDynamicSharedMemorySize, GEMM_SMEM);
        cudaFuncSetAttribute(mma_gemm<1>, cudaFuncAttributeMaxDynamicSharedMemorySize, GEMM_SMEM);
        cudaFuncSetAttribute(mma_gemm<2>, cudaFuncAttributeMaxDynamicSharedMemorySize, GEMM_SMEM);
        cudaFuncSetAttribute(mma_gemm<3>, cudaFuncAttributeMaxDynamicSharedMemorySize, GEMM_SMEM);
    }

    // 0) operand prep: split x, transpose+split weights
    split_kernel<<<(TCNT*IND/4 + 255)/256, 256>>>(x, p_xh, p_xl, TCNT*IND/4);
    tsplit_kernel<<<dim3(ED/32, IND/32), 256>>>(w_in,   p_wiTh,  p_wiTl,  IND,   ED);
    tsplit_kernel<<<dim3(UP2/32, ED/32), 256>>>(w_up,   p_wupTh, p_wupTl, ED,    UP2);
    tsplit_kernel<<<dim3(ED/32, INNER/32), 256>>>(w_down, p_wdTh, p_wdTl, INNER, ED);

    // 1) h_in = x @ w_in + b_in
    mma_gemm<0><<<dim3(ED/128, TCNT/128, 1), 256, GEMM_SMEM>>>(p_xh, p_xl, p_wiTh, p_wiTl,
        p_hin, nullptr, nullptr, IND, IND, IND, ED,
        b_in, nullptr, nullptr, nullptr, nullptr, nullptr);
    // 2) xn = LN(h_in)*ln1_w -> bf16 hi/lo
    ln_split_kernel<<<TCNT, 256>>>(p_hin, ln1_w, p_lnh, p_lnl);
    // 3) up = xn @ w_up + b_up
    mma_gemm<0><<<dim3(UP2/128, TCNT/128, 1), 256, GEMM_SMEM>>>(p_lnh, p_lnl, p_wupTh, p_wupTl,
        p_up, nullptr, nullptr, ED, ED, ED, UP2,
        b_up, nullptr, nullptr, nullptr, nullptr, nullptr);
    // 4) causal conv + SiLU
    conv_silu_kernel<<<(TCNT*INNER)/256, 256>>>(p_up, conv_w, conv_b, p_xca);
    // 5) block-diagonal q/k/v (+ bf16 splits of q,k)
    headwise_kernel<<<(TCNT*NHW)/256, 256>>>(p_xca, p_up, q_w, q_b, k_w, k_b, v_w, v_b,
                                             p_q, p_k, p_v, p_qh, p_ql, p_kh, p_kl);
    // 6) gates
    gates_kernel<<<TCNT/GTOK, 256>>>(p_q, p_k, p_v, ig_w, ig_b, fg_w, fg_b, p_ig, p_fg);
    // 7) per-head scans
    scan_kernel<<<ZB, 256>>>(p_fg, p_ig, p_cum, p_m);
    // 7b) v transpose+split per head
    vtrans_kernel<<<dim3(SEQ/32, DH/32, ZB), 256>>>(p_v, p_vTh, p_vTl);
    // 8) C = (q@k^T/sqrt(DH)) * decay, causal -> bf16 hi/lo
    mma_gemm<2><<<dim3(SEQ/128, SEQ/128, ZB), 256, GEMM_SMEM>>>(p_qh, p_ql, p_kh, p_kl,
        nullptr, p_Ch, p_Cl, DH, INNER, INNER, SEQ,
        nullptr, nullptr, p_cum, p_ig, p_m, nullptr);
    // 9) row normalizer
    rowsum_kernel<<<ZB*SEQ, 256>>>(p_Ch, p_Cl, p_m, p_in2);
    // 10) h = diag(invn) * C @ v
    mma_gemm<3><<<dim3(DH/128, SEQ/128, ZB), 256, GEMM_SMEM>>>(p_Ch, p_Cl, p_vTh, p_vTl,
        p_h, nullptr, nullptr, SEQ, SEQ, SEQ, DH,
        nullptr, nullptr, nullptr, nullptr, nullptr, p_in2);
    // 11) head-norm + skip + output gate -> bf16 hi/lo
    headnorm_gate_kernel<<<TCNT*NH, 128>>>(p_h, onorm_w, skipv, p_xca, p_up, p_gh, p_gl);
    // 12) yt = g @ w_down + b_down + h_in
    mma_gemm<1><<<dim3(ED/128, TCNT/128, 1), 256, GEMM_SMEM>>>(p_gh, p_gl, p_wdTh, p_wdTl,
        p_yt, nullptr, nullptr, INNER, INNER, INNER, ED,
        b_down, p_hin, nullptr, nullptr, nullptr, nullptr);
    // 13) out = LN(yt)*post_w
    ln_kernel<<<TCNT, 256>>>(p_yt, post_w, (float*)d_out);
}

// round 15
// speedup vs baseline: 2.4526x; 1.1736x over previous
#include <cuda_runtime.h>
#include <cuda_bf16.h>
#include <stdint.h>
#include <math.h>

// ---------------- fixed problem dims ----------------
#define BATCH 2
#define SEQ   2048
#define TCNT  4096        // BATCH*SEQ
#define IND   512
#define ED    1024
#define INNER 2048
#define UP2   4096        // 2*INNER
#define NH    4
#define DH    512
#define NHW   512
#define ZB    8           // BATCH*NH

// ---------------- scratch (bss, no allocation) ----------------
__device__ float g_hin[TCNT*ED];
__device__ float g_up [(size_t)TCNT*UP2];
__device__ float g_xca[TCNT*INNER];
__device__ float g_v  [TCNT*INNER];
__device__ float g_ig [ZB*SEQ];
__device__ float g_fg [ZB*SEQ];
__device__ float g_cum[ZB*SEQ];
__device__ float g_m  [ZB*SEQ];
__device__ float g_in2[ZB*SEQ];
__device__ float g_ps [(size_t)ZB*SEQ*64];   // per-row 32-col-subtile partial sums (4MB)
__device__ float g_h  [(size_t)ZB*SEQ*DH];
__device__ float g_yt [TCNT*ED];

// bf16 split operands
__device__ __nv_bfloat16 g_xh [TCNT*IND],  g_xl [TCNT*IND];
__device__ __nv_bfloat16 g_wiTh[ED*IND],   g_wiTl[ED*IND];
__device__ __nv_bfloat16 g_lnh[TCNT*ED],   g_lnl[TCNT*ED];
__device__ __nv_bfloat16 g_wupTh[(size_t)UP2*ED], g_wupTl[(size_t)UP2*ED];
__device__ __nv_bfloat16 g_qh [TCNT*INNER], g_ql [TCNT*INNER];
__device__ __nv_bfloat16 g_kh [TCNT*INNER], g_kl [TCNT*INNER];
__device__ __nv_bfloat16 g_vTh[(size_t)ZB*DH*SEQ], g_vTl[(size_t)ZB*DH*SEQ];
__device__ __nv_bfloat16 g_Ch [(size_t)ZB*SEQ*SEQ], g_Cl [(size_t)ZB*SEQ*SEQ];
__device__ __nv_bfloat16 g_gh [TCNT*INNER], g_gl [TCNT*INNER];
__device__ __nv_bfloat16 g_wdTh[(size_t)ED*INNER], g_wdTl[(size_t)ED*INNER];

// ---------------- PTX helpers (mma.sync / ldmatrix / cp.async; plain sm_80+ PTX) ----------------
__device__ __forceinline__ uint32_t smem_u32(const void* p) {
    uint32_t a;
    asm("{ .reg .u64 t; cvta.to.shared.u64 t, %1; cvt.u32.u64 %0, t; }" : "=r"(a) : "l"(p));
    return a;
}

#define LDSM_X4(r0,r1,r2,r3,addr) \
    asm volatile("ldmatrix.sync.aligned.m8n8.x4.shared.b16 {%0,%1,%2,%3}, [%4];" \
        : "=r"(r0), "=r"(r1), "=r"(r2), "=r"(r3) : "r"(addr))

#define CP16(dst,src) \
    asm volatile("cp.async.cg.shared.global [%0], [%1], 16;" :: "r"(dst), "l"(src))
#define CP_COMMIT() asm volatile("cp.async.commit_group;" ::: "memory")

__device__ __forceinline__ void mma_bf16(float* d, const uint32_t* a, const uint32_t* b) {
    asm volatile("mma.sync.aligned.m16n8k16.row.col.f32.bf16.bf16.f32 "
        "{%0,%1,%2,%3}, {%4,%5,%6,%7}, {%8,%9}, {%0,%1,%2,%3};"
        : "+f"(d[0]), "+f"(d[1]), "+f"(d[2]), "+f"(d[3])
        : "r"(a[0]), "r"(a[1]), "r"(a[2]), "r"(a[3]), "r"(b[0]), "r"(b[1]));
}

__device__ __forceinline__ void bf_split(float x, __nv_bfloat16& hi, __nv_bfloat16& lo) {
    hi = __float2bfloat16_rn(x);
    lo = __float2bfloat16_rn(x - __bfloat162float(hi));
}

// ---------------- HMMA GEMM: 128x128 tile, K-chunks of 32 (hi|lo packed 128B rows) ----------------
// 3-stage cp.async pipeline, one __syncthreads per chunk.
// EPI 0: Cf = A@B + bias[n]
// EPI 1: Cf = A@B + bias[n] + addm[m,n]
// EPI 2: per-head qk decay epilogue (smem ea/eb factorization) -> Coh/Col split + row partials into Cf(=ps)
// EPI 3: per-head C@v, k-limit m0+128 (y flipped for tail packing), row-scaled by invn[i] -> Cf
#define KB 32
#define TILE_BYTES 16384   // 128 rows * 128B
#define GEMM_SMEM (6*TILE_BYTES)   // 3-stage double operand

template<int EPI>
__global__ void __launch_bounds__(256)
mma_gemm(const __nv_bfloat16* __restrict__ Ah, const __nv_bfloat16* __restrict__ Al,
         const __nv_bfloat16* __restrict__ Bh, const __nv_bfloat16* __restrict__ Bl,
         float* __restrict__ Cf, __nv_bfloat16* __restrict__ Coh, __nv_bfloat16* __restrict__ Col,
         int K, int lda, int ldb, int ldc,
         const float* __restrict__ bias, const float* __restrict__ addm,
         const float* __restrict__ cumv, const float* __restrict__ igv,
         const float* __restrict__ mvv,  const float* __restrict__ invn)
{
    const int m0 = ((EPI == 3) ? (gridDim.y - 1 - blockIdx.y) : blockIdx.y) * 128;
    const int n0 = blockIdx.x * 128;
    if (EPI == 2 && n0 > m0) return;
    const int z = blockIdx.z;

    if (EPI == 2) {
        int b = z >> 2, h = z & 3;
        size_t o = ((size_t)b * SEQ) * INNER + (size_t)h * DH;
        Ah += o; Al += o; Bh += o; Bl += o;
    } else if (EPI == 3) {
        size_t ao = (size_t)z * SEQ * SEQ;
        size_t bo = (size_t)z * DH * SEQ;
        Ah += ao; Al += ao; Bh += bo; Bl += bo;
        Cf += (size_t)z * SEQ * DH;
    }
    const int kend = (EPI == 3) ? (m0 + 128) : K;
    const int NC = kend / KB;

    extern __shared__ __align__(1024) char smem[];
    const uint32_t smemb = smem_u32(smem);
    // layout: sA[0..2], sB[0..2], each TILE_BYTES

    const int tid  = threadIdx.x;
    const int lane = tid & 31, wid = tid >> 5;
    const int wm = wid & 1, wn = wid >> 1;
    const int rr = lane & 7, q = lane >> 3;
    const int g  = lane >> 2, t = lane & 3;

    float acc[4][4][4];
    #pragma unroll
    for (int i = 0; i < 4; i++)
        #pragma unroll
        for (int j = 0; j < 4; j++)
            #pragma unroll
            for (int e = 0; e < 4; e++) acc[i][j][e] = 0.f;

    auto issue = [&](int c) {
        const int bsel = c % 3;
        const int k0 = c * KB;
        const uint32_t dA = smemb + bsel * TILE_BYTES;
        const uint32_t dB = smemb + 3 * TILE_BYTES + bsel * TILE_BYTES;
        #pragma unroll
        for (int it = 0; it < 8; it++) {
            int u = it * 256 + tid;          // 0..2047 (1024 16B-chunks per tile)
            int tile = u >> 10;
            int uu = u & 1023;
            int r = uu >> 3, col = uu & 7;   // col 0..3 hi, 4..7 lo
            const __nv_bfloat16* src;
            if (tile == 0) src = ((col < 4) ? Ah : Al) + (size_t)(m0 + r) * lda + k0 + (col & 3) * 8;
            else           src = ((col < 4) ? Bh : Bl) + (size_t)(n0 + r) * ldb + k0 + (col & 3) * 8;
            uint32_t dst = (tile ? dB : dA) + r * 128 + ((col ^ (r & 7)) << 4);
            CP16(dst, (const void*)src);
        }
        CP_COMMIT();
    };

    issue(0);
    if (NC > 1) issue(1);
    for (int c = 0; c < NC; c++) {
        if (c + 1 < NC) { asm volatile("cp.async.wait_group 1;" ::: "memory"); }
        else            { asm volatile("cp.async.wait_group 0;" ::: "memory"); }
        __syncthreads();
        if (c + 2 < NC) issue(c + 2);
        const int bsel = c % 3;
        const uint32_t baseA = smemb + bsel * TILE_BYTES;
        const uint32_t baseB = smemb + 3 * TILE_BYTES + bsel * TILE_BYTES;
        #pragma unroll
        for (int khalf = 0; khalf < 2; khalf++) {
            const int kch = 2 * khalf;       // hi 16B cols
            const int kcl = 4 + 2 * khalf;   // lo 16B cols
            uint32_t Bh_[4][2], Bl_[4][2];
            #pragma unroll
            for (int p = 0; p < 2; p++) {
                int rB = wn * 32 + p * 16 + rr + (q >> 1) * 8;
                uint32_t ah = baseB + rB * 128 + (((kch + (q & 1)) ^ (rB & 7)) << 4);
                LDSM_X4(Bh_[2*p][0], Bh_[2*p][1], Bh_[2*p+1][0], Bh_[2*p+1][1], ah);
                uint32_t al = baseB + rB * 128 + (((kcl + (q & 1)) ^ (rB & 7)) << 4);
                LDSM_X4(Bl_[2*p][0], Bl_[2*p][1], Bl_[2*p+1][0], Bl_[2*p+1][1], al);
            }
            uint32_t Af[4][4];
            #pragma unroll
            for (int mi = 0; mi < 4; mi++) {
                int rA = wm * 64 + mi * 16 + rr + (q & 1) * 8;
                uint32_t aa = baseA + rA * 128 + (((kch + (q >> 1)) ^ (rA & 7)) << 4);
                LDSM_X4(Af[mi][0], Af[mi][1], Af[mi][2], Af[mi][3], aa);
            }
            #pragma unroll
            for (int mi = 0; mi < 4; mi++)
                #pragma unroll
                for (int ni = 0; ni < 4; ni++) {
                    mma_bf16(acc[mi][ni], Af[mi], Bh_[ni]);   // hi*hi
                    mma_bf16(acc[mi][ni], Af[mi], Bl_[ni]);   // hi*lo
                }
            #pragma unroll
            for (int mi = 0; mi < 4; mi++) {
                int rA = wm * 64 + mi * 16 + rr + (q & 1) * 8;
                uint32_t aa = baseA + rA * 128 + (((kcl + (q >> 1)) ^ (rA & 7)) << 4);
                LDSM_X4(Af[mi][0], Af[mi][1], Af[mi][2], Af[mi][3], aa);
            }
            #pragma unroll
            for (int mi = 0; mi < 4; mi++)
                #pragma unroll
                for (int ni = 0; ni < 4; ni++)
                    mma_bf16(acc[mi][ni], Af[mi], Bh_[ni]);   // lo*hi
        }
        __syncthreads();
    }

    // ---------------- epilogues ----------------
    if (EPI == 2) {
        const float* cu = cumv + z*SEQ;
        const float* ip = igv  + z*SEQ;
        const float* mv = mvv  + z*SEQ;
        const float SC = 0.04419417382415922f; // 1/sqrt(512)
        __shared__ float ebs[128], eas[128], rsm[8];
        float bv = (tid < 128) ? (ip[n0 + tid] - cu[n0 + tid]) : -3.0e38f;
        float mx = bv;
        #pragma unroll
        for (int o = 16; o > 0; o >>= 1) mx = fmaxf(mx, __shfl_down_sync(0xffffffffu, mx, o));
        if ((tid & 31) == 0) rsm[tid >> 5] = mx;
        __syncthreads();
        if (tid == 0) {
            float r = rsm[0];
            #pragma unroll
            for (int i = 1; i < 8; i++) r = fmaxf(r, rsm[i]);
            rsm[0] = r;
        }
        __syncthreads();
        float bmax = rsm[0];
        if (tid < 128) ebs[tid] = __expf(bv - bmax);
        else {
            int mm = m0 + tid - 128;
            eas[tid - 128] = __expf(cu[mm] - mv[mm] + bmax) * SC;
        }
        __syncthreads();
        #pragma unroll
        for (int mi = 0; mi < 4; mi++)
        #pragma unroll
        for (int h = 0; h < 2; h++) {
            int m = m0 + wm * 64 + mi * 16 + g + 8 * h;
            float ea = eas[m - m0];
            size_t base = (size_t)z*SEQ*SEQ + (size_t)m*SEQ;
            float rsum = 0.f;
            #pragma unroll
            for (int ni = 0; ni < 4; ni++) {
                int n = n0 + wn * 32 + ni * 8 + 2 * t;
                float v0 = (n+0 <= m) ? acc[mi][ni][2*h+0] * ea * ebs[n - n0]   : 0.f;
                float v1 = (n+1 <= m) ? acc[mi][ni][2*h+1] * ea * ebs[n+1 - n0] : 0.f;
                rsum += v0 + v1;
                __nv_bfloat16 h0, l0, h1, l1;
                bf_split(v0, h0, l0); bf_split(v1, h1, l1);
                __nv_bfloat162 hh; hh.x = h0; hh.y = h1;
                __nv_bfloat162 ll; ll.x = l0; ll.y = l1;
                *(__nv_bfloat162*)(Coh + base + n) = hh;
                *(__nv_bfloat162*)(Col + base + n) = ll;
            }
            rsum += __shfl_xor_sync(0xffffffffu, rsum, 1);
            rsum += __shfl_xor_sync(0xffffffffu, rsum, 2);
            if (t == 0)
                Cf[(((size_t)z*SEQ + m) << 6) + (n0 >> 5) + wn] = rsum;  // Cf = ps buffer
        }
    } else {
        #pragma unroll
        for (int mi = 0; mi < 4; mi++)
        #pragma unroll
        for (int h = 0; h < 2; h++) {
            int m = m0 + wm * 64 + mi * 16 + g + 8 * h;
            if (EPI == 0 || EPI == 1) {
                #pragma unroll
                for (int ni = 0; ni < 4; ni++) {
                    int n = n0 + wn * 32 + ni * 8 + 2 * t;
                    float2 o;
                    o.x = acc[mi][ni][2*h+0] + bias[n];
                    o.y = acc[mi][ni][2*h+1] + bias[n+1];
                    if (EPI == 1) {
                        float2 ad = *(const float2*)(addm + (size_t)m*ldc + n);
                        o.x += ad.x; o.y += ad.y;
                    }
                    *(float2*)(Cf + (size_t)m*ldc + n) = o;
                }
            } else { // EPI 3
                float s = invn[z*SEQ + m];
                #pragma unroll
                for (int ni = 0; ni < 4; ni++) {
                    int n = n0 + wn * 32 + ni * 8 + 2 * t;
                    float2 o;
                    o.x = acc[mi][ni][2*h+0] * s;
                    o.y = acc[mi][ni][2*h+1] * s;
                    *(float2*)(Cf + (size_t)m*ldc + n) = o;
                }
            }
        }
    }
}

// ---------------- rowfix: sum deterministic partials -> invn ----------------
__global__ void rowfix_kernel(const float* __restrict__ ps, const float* __restrict__ mvv,
                              float* __restrict__ invn)
{
    int row = blockIdx.x * 256 + threadIdx.x;   // < ZB*SEQ
    int m = row & (SEQ-1);
    int ne = ((m >> 7) + 1) << 2;               // valid 32-col subtiles
    const float* p = ps + ((size_t)row << 6);
    float s = 0.f;
    for (int i = 0; i < ne; i++) s += p[i];
    float nrm = fmaxf(fabsf(s), __expf(-mvv[row]));
    invn[row] = 1.f / (nrm + 1e-6f);
}

// ---------------- helpers ----------------
__device__ __forceinline__ float blockReduceSum(float v, float* sm) {
    int tid = threadIdx.x;
    __syncthreads();
    #pragma unroll
    for (int o = 16; o > 0; o >>= 1) v += __shfl_down_sync(0xffffffffu, v, o);
    if ((tid & 31) == 0) sm[tid >> 5] = v;
    __syncthreads();
    int nw = blockDim.x >> 5;
    float r = (tid < nw) ? sm[tid] : 0.f;
    if (tid < 32) {
        #pragma unroll
        for (int o = 16; o > 0; o >>= 1) r += __shfl_down_sync(0xffffffffu, r, o);
        if (tid == 0) sm[0] = r;
    }
    __syncthreads();
    return sm[0];
}

// ---------------- elementwise split: x -> hi/lo bf16 ----------------
__global__ void split_kernel(const float* __restrict__ x,
                             __nv_bfloat16* __restrict__ hi, __nv_bfloat16* __restrict__ lo, int n4)
{
    int i = blockIdx.x*256 + threadIdx.x;
    if (i >= n4) return;
    float4 v = *(const float4*)(x + i*4);
    __nv_bfloat16 h0,l0,h1,l1,h2,l2,h3,l3;
    bf_split(v.x,h0,l0); bf_split(v.y,h1,l1); bf_split(v.z,h2,l2); bf_split(v.w,h3,l3);
    __nv_bfloat162 a,b; a.x=h0;a.y=h1; b.x=h2;b.y=h3;
    *(__nv_bfloat162*)(hi + i*4) = a; *(__nv_bfloat162*)(hi + i*4 + 2) = b;
    a.x=l0;a.y=l1; b.x=l2;b.y=l3;
    *(__nv_bfloat162*)(lo + i*4) = a; *(__nv_bfloat162*)(lo + i*4 + 2) = b;
}

// ---------------- transpose + split: W [R,Cc] f32 -> Wt hi/lo [Cc,R] bf16 ----------------
__global__ void tsplit_kernel(const float* __restrict__ W,
                              __nv_bfloat16* __restrict__ Th, __nv_bfloat16* __restrict__ Tl,
                              int R, int Cc)
{
    __shared__ float tile[32][33];
    int r0 = blockIdx.y*32, c0 = blockIdx.x*32;
    int tx = threadIdx.x & 31, ty = threadIdx.x >> 5;   // 256 threads
    for (int i = ty; i < 32; i += 8)
        tile[i][tx] = W[(size_t)(r0+i)*Cc + c0 + tx];
    __syncthreads();
    for (int i = ty; i < 32; i += 8) {
        float v = tile[tx][i];           // = W[r0+tx][c0+i]
        __nv_bfloat16 h, l; bf_split(v, h, l);
        size_t o = (size_t)(c0+i)*R + r0 + tx;
        Th[o] = h; Tl[o] = l;
    }
}

// ---------------- per-head v transpose + split: v[T,INNER] -> vT[z][n][j] ----------------
__global__ void vtrans_kernel(const float* __restrict__ v,
                              __nv_bfloat16* __restrict__ Th, __nv_bfloat16* __restrict__ Tl)
{
    int z = blockIdx.z; int b = z >> 2, h = z & 3;
    int j0 = blockIdx.x*32, n0 = blockIdx.y*32;
    __shared__ float tile[32][33];
    int tx = threadIdx.x & 31, ty = threadIdx.x >> 5;
    for (int i = ty; i < 32; i += 8)
        tile[i][tx] = v[(size_t)(b*SEQ + j0 + i)*INNER + h*DH + n0 + tx];
    __syncthreads();
    for (int i = ty; i < 32; i += 8) {
        float val = tile[tx][i];         // v[j0+tx][n0+i]
        __nv_bfloat16 hh, ll; bf_split(val, hh, ll);
        size_t o = (size_t)z*DH*SEQ + (size_t)(n0+i)*SEQ + j0 + tx;
        Th[o] = hh; Tl[o] = ll;
    }
}

// ---------------- LayerNorm -> bf16 hi/lo split (width 1024) ----------------
__global__ void ln_split_kernel(const float* __restrict__ x, const float* __restrict__ w,
                                __nv_bfloat16* __restrict__ yh, __nv_bfloat16* __restrict__ yl)
{
    int r = blockIdx.x, tid = threadIdx.x;   // 256 threads
    const float* xr = x + (size_t)r*ED;
    float4 v = *(const float4*)(xr + tid*4);
    float s = v.x + v.y + v.z + v.w;
    float q = v.x*v.x + v.y*v.y + v.z*v.z + v.w*v.w;
    __shared__ float sm[8];
    s = blockReduceSum(s, sm);
    q = blockReduceSum(q, sm);
    float mean = s * (1.f/ED);
    float var  = q * (1.f/ED) - mean*mean;
    float rstd = rsqrtf(var + 1e-5f);
    float4 wv = *(const float4*)(w + tid*4);
    float o0 = (v.x - mean)*rstd*wv.x, o1 = (v.y - mean)*rstd*wv.y;
    float o2 = (v.z - mean)*rstd*wv.z, o3 = (v.w - mean)*rstd*wv.w;
    __nv_bfloat16 h0,l0,h1,l1,h2,l2,h3,l3;
    bf_split(o0,h0,l0); bf_split(o1,h1,l1); bf_split(o2,h2,l2); bf_split(o3,h3,l3);
    size_t base = (size_t)r*ED + tid*4;
    __nv_bfloat162 a; a.x=h0;a.y=h1; *(__nv_bfloat162*)(yh+base)=a;
    a.x=h2;a.y=h3; *(__nv_bfloat162*)(yh+base+2)=a;
    a.x=l0;a.y=l1; *(__nv_bfloat162*)(yl+base)=a;
    a.x=l2;a.y=l3; *(__nv_bfloat162*)(yl+base+2)=a;
}

// ---------------- plain f32 LayerNorm (final output) ----------------
__global__ void ln_kernel(const float* __restrict__ x, const float* __restrict__ w,
                          float* __restrict__ y)
{
    int r = blockIdx.x, tid = threadIdx.x;
    const float* xr = x + (size_t)r*ED;
    float4 v = *(const float4*)(xr + tid*4);
    float s = v.x + v.y + v.z + v.w;
    float q = v.x*v.x + v.y*v.y + v.z*v.z + v.w*v.w;
    __shared__ float sm[8];
    s = blockReduceSum(s, sm);
    q = blockReduceSum(q, sm);
    float mean = s * (1.f/ED);
    float var  = q * (1.f/ED) - mean*mean;
    float rstd = rsqrtf(var + 1e-5f);
    float4 wv = *(const float4*)(w + tid*4);
    float4 o;
    o.x = (v.x - mean)*rstd*wv.x; o.y = (v.y - mean)*rstd*wv.y;
    o.z = (v.z - mean)*rstd*wv.z; o.w = (v.w - mean)*rstd*wv.w;
    *(float4*)(y + (size_t)r*ED + tid*4) = o;
}

// ---------------- causal depthwise conv (K=4) + SiLU ----------------
__global__ void conv_silu_kernel(const float* __restrict__ up, const float* __restrict__ cw,
                                 const float* __restrict__ cb, float* __restrict__ xca)
{
    int idx = blockIdx.x*256 + threadIdx.x;   // < TCNT*INNER
    int c = idx & (INNER-1);
    int t = idx >> 11;
    int s = t & (SEQ-1);
    float acc = cb[c];
    const float* w = cw + c*4;
    #pragma unroll
    for (int kk = 0; kk < 4; kk++) {
        int ss = s - 3 + kk;
        if (ss >= 0) acc = fmaf(up[(size_t)(t - 3 + kk)*UP2 + c], w[kk], acc);
    }
    xca[idx] = acc / (1.f + __expf(-acc));
}

// ---------------- fused headwise q/k/v + gate projections ----------------
// one block = GTOK tokens, 512 threads (thread = one 4-channel block).
#define GTOK 4
__global__ void __launch_bounds__(512)
hwg_kernel(const float* __restrict__ xca, const float* __restrict__ up,
    const float* __restrict__ qw, const float* __restrict__ qb,
    const float* __restrict__ kw, const float* __restrict__ kb,
    const float* __restrict__ vw, const float* __restrict__ vb,
    const float* __restrict__ igw, const float* __restrict__ igb,
    const float* __restrict__ fgw, const float* __restrict__ fgb,
    float* __restrict__ v,
    __nv_bfloat16* __restrict__ qh, __nv_bfloat16* __restrict__ ql,
    __nv_bfloat16* __restrict__ kh, __nv_bfloat16* __restrict__ kl,
    float* __restrict__ igo, float* __restrict__ fgo)
{
    int tid = threadIdx.x;                    // 0..511 = channel-block
    int lane = tid & 31, wid = tid >> 5;
    int t0 = blockIdx.x * GTOK;
    int co = tid * 4;
    __shared__ float wsum[16][8];
    const float* qwp = qw + tid*16;
    const float* kwp = kw + tid*16;
    const float* vwp = vw + tid*16;
    float qb_[4], kb_[4], vb_[4];
    { float4 a = *(const float4*)(qb + co); qb_[0]=a.x;qb_[1]=a.y;qb_[2]=a.z;qb_[3]=a.w; }
    { float4 a = *(const float4*)(kb + co); kb_[0]=a.x;kb_[1]=a.y;kb_[2]=a.z;kb_[3]=a.w; }
    { float4 a = *(const float4*)(vb + co); vb_[0]=a.x;vb_[1]=a.y;vb_[2]=a.z;vb_[3]=a.w; }

    for (int tt = 0; tt < GTOK; tt++) {
        int tok = t0 + tt;
        float4 xc = *(const float4*)(xca + (size_t)tok*INNER + co);
        float4 xm = *(const float4*)(up  + (size_t)tok*UP2   + co);
        float xcv[4] = {xc.x, xc.y, xc.z, xc.w};
        float xmv[4] = {xm.x, xm.y, xm.z, xm.w};
        float qo[4], ko[4], vo[4];
        #pragma unroll
        for (int o = 0; o < 4; o++) {
            float aq = qb_[o], ak = kb_[o], av = vb_[o];
            #pragma unroll
            for (int d = 0; d < 4; d++) {
                aq = fmaf(xcv[d], qwp[o*4+d], aq);
                ak = fmaf(xcv[d], kwp[o*4+d], ak);
                av = fmaf(xmv[d], vwp[o*4+d], av);
            }
            qo[o] = aq; ko[o] = ak; vo[o] = av;
        }
        size_t base = (size_t)tok*INNER + co;
        *(float4*)(v + base) = make_float4(vo[0],vo[1],vo[2],vo[3]);
        __nv_bfloat16 h0,l0,h1,l1,h2,l2,h3,l3;
        bf_split(qo[0],h0,l0); bf_split(qo[1],h1,l1); bf_split(qo[2],h2,l2); bf_split(qo[3],h3,l3);
        __nv_bfloat162 a; a.x=h0;a.y=h1; *(__nv_bfloat162*)(qh+base)=a;
        a.x=h2;a.y=h3; *(__nv_bfloat162*)(qh+base+2)=a;
        a.x=l0;a.y=l1; *(__nv_bfloat162*)(ql+base)=a;
        a.x=l2;a.y=l3; *(__nv_bfloat162*)(ql+base+2)=a;
        bf_split(ko[0],h0,l0); bf_split(ko[1],h1,l1); bf_split(ko[2],h2,l2); bf_split(ko[3],h3,l3);
        a.x=h0;a.y=h1; *(__nv_bfloat162*)(kh+base)=a;
        a.x=h2;a.y=h3; *(__nv_bfloat162*)(kh+base+2)=a;
        a.x=l0;a.y=l1; *(__nv_bfloat162*)(kl+base)=a;
        a.x=l2;a.y=l3; *(__nv_bfloat162*)(kl+base+2)=a;

        // gate partials: concat(q,k,v) rows of igw/fgw
        float li[4] = {0,0,0,0}, lf[4] = {0,0,0,0};
        #pragma unroll
        for (int d = 0; d < 4; d++) {
            float4 wq = *(const float4*)(igw + (size_t)(co+d)*4);
            float4 wk = *(const float4*)(igw + (size_t)(INNER+co+d)*4);
            float4 wv4= *(const float4*)(igw + (size_t)(2*INNER+co+d)*4);
            li[0] = fmaf(qo[d], wq.x, fmaf(ko[d], wk.x, fmaf(vo[d], wv4.x, li[0])));
            li[1] = fmaf(qo[d], wq.y, fmaf(ko[d], wk.y, fmaf(vo[d], wv4.y, li[1])));
            li[2] = fmaf(qo[d], wq.z, fmaf(ko[d], wk.z, fmaf(vo[d], wv4.z, li[2])));
            li[3] = fmaf(qo[d], wq.w, fmaf(ko[d], wk.w, fmaf(vo[d], wv4.w, li[3])));
            float4 fq = *(const float4*)(fgw + (size_t)(co+d)*4);
            float4 fk = *(const float4*)(fgw + (size_t)(INNER+co+d)*4);
            float4 fv = *(const float4*)(fgw + (size_t)(2*INNER+co+d)*4);
            lf[0] = fmaf(qo[d], fq.x, fmaf(ko[d], fk.x, fmaf(vo[d], fv.x, lf[0])));
            lf[1] = fmaf(qo[d], fq.y, fmaf(ko[d], fk.y, fmaf(vo[d], fv.y, lf[1])));
            lf[2] = fmaf(qo[d], fq.z, fmaf(ko[d], fk.z, fmaf(vo[d], fv.z, lf[2])));
            lf[3] = fmaf(qo[d], fq.w, fmaf(ko[d], fk.w, fmaf(vo[d], fv.w, lf[3])));
        }
        #pragma unroll
        for (int o = 16; o > 0; o >>= 1) {
            #pragma unroll
            for (int n = 0; n < 4; n++) {
                li[n] += __shfl_down_sync(0xffffffffu, li[n], o);
                lf[n] += __shfl_down_sync(0xffffffffu, lf[n], o);
            }
        }
        if (lane == 0) {
            #pragma unroll
            for (int n = 0; n < 4; n++) { wsum[wid][n] = li[n]; wsum[wid][4+n] = lf[n]; }
        }
        __syncthreads();
        if (tid < 8) {
            float s = 0.f;
            #pragma unroll
            for (int w = 0; w < 16; w++) s += wsum[w][tid];
            int b = tok >> 11, sidx = tok & (SEQ-1);
            if (tid < 4) igo[(b*NH + tid)*SEQ + sidx]     = s + igb[tid];
            else         fgo[(b*NH + (tid-4))*SEQ + sidx] = s + fgb[tid-4];
        }
        __syncthreads();
    }
}

// ---------------- per-head scans ----------------
__global__ void scan_kernel(const float* __restrict__ fgv, const float* __restrict__ igv,
                            float* __restrict__ cumv, float* __restrict__ mvv)
{
    int z = blockIdx.x, tid = threadIdx.x;   // 256 threads
    __shared__ float sc[SEQ];
    __shared__ float sa[SEQ];
    __shared__ float aux[256];
    const float* fg = fgv + z*SEQ;
    const float* ig = igv + z*SEQ;
    for (int s = tid; s < SEQ; s += 256) {
        float xx = fg[s];
        sc[s] = (xx >= 0.f) ? -log1pf(expf(-xx)) : (xx - log1pf(expf(xx)));
    }
    __syncthreads();
    {
        float vloc[8]; float run = 0.f; int base = tid*8;
        #pragma unroll
        for (int i = 0; i < 8; i++) { run += sc[base+i]; vloc[i] = run; }
        aux[tid] = run;
        __syncthreads();
        for (int off = 1; off < 256; off <<= 1) {
            float add = (tid >= off) ? aux[tid-off] : 0.f;
            __syncthreads();
            aux[tid] += add;
            __syncthreads();
        }
        float pre = (tid > 0) ? aux[tid-1] : 0.f;
        #pragma unroll
        for (int i = 0; i < 8; i++) sc[base+i] = vloc[i] + pre;
    }
    __syncthreads();
    for (int s = tid; s < SEQ; s += 256) sa[s] = ig[s] - sc[s];
    __syncthreads();
    {
        float vloc[8]; float run = -INFINITY; int base = tid*8;
        #pragma unroll
        for (int i = 0; i < 8; i++) { run = fmaxf(run, sa[base+i]); vloc[i] = run; }
        aux[tid] = run;
        __syncthreads();
        for (int off = 1; off < 256; off <<= 1) {
            float add = (tid >= off) ? aux[tid-off] : -INFINITY;
            __syncthreads();
            aux[tid] = fmaxf(aux[tid], add);
            __syncthreads();
        }
        float pre = (tid > 0) ? aux[tid-1] : -INFINITY;
        #pragma unroll
        for (int i = 0; i < 8; i++) sa[base+i] = fmaxf(vloc[i], pre);
    }
    __syncthreads();
    for (int s = tid; s < SEQ; s += 256) {
        cumv[z*SEQ + s] = sc[s];
        mvv [z*SEQ + s] = sc[s] + sa[s];
    }
}

// ---------------- head-norm + skip + output gate -> bf16 hi/lo split ----------------
__global__ void headnorm_gate_kernel(const float* __restrict__ hb_, const float* __restrict__ ow,
    const float* __restrict__ skipv, const float* __restrict__ xca,
    const float* __restrict__ up,
    __nv_bfloat16* __restrict__ gh, __nv_bfloat16* __restrict__ gl)
{
    int idx = blockIdx.x;                    // t*NH + h
    int h = idx & 3, t = idx >> 2;
    int b = t >> 11, s = t & (SEQ-1);
    const float* hr = hb_ + ((size_t)(b*NH + h)*SEQ + s)*DH;
    int tid = threadIdx.x;                   // 128 threads * 4 = 512
    float4 hv = *(const float4*)(hr + tid*4);
    float sum = hv.x + hv.y + hv.z + hv.w;
    float sq  = hv.x*hv.x + hv.y*hv.y + hv.z*hv.z + hv.w*hv.w;
    __shared__ float sm[4];
    sum = blockReduceSum(sum, sm);
    sq  = blockReduceSum(sq, sm);
    float mean = sum * (1.f/DH);
    float var  = sq * (1.f/DH) - mean*mean;
    float rstd = rsqrtf(var + 1e-5f);
    int c = h*DH + tid*4;
    float4 owv = *(const float4*)(ow + c);
    float4 sk  = *(const float4*)(skipv + c);
    float4 xc  = *(const float4*)(xca + (size_t)t*INNER + c);
    float4 zv  = *(const float4*)(up + (size_t)t*UP2 + INNER + c);
    float o0 = ((hv.x-mean)*rstd*owv.x + sk.x*xc.x) * (zv.x / (1.f + __expf(-zv.x)));
    float o1 = ((hv.y-mean)*rstd*owv.y + sk.y*xc.y) * (zv.y / (1.f + __expf(-zv.y)));
    float o2 = ((hv.z-mean)*rstd*owv.z + sk.z*xc.z) * (zv.z / (1.f + __expf(-zv.z)));
    float o3 = ((hv.w-mean)*rstd*owv.w + sk.w*xc.w) * (zv.w / (1.f + __expf(-zv.w)));
    size_t base = (size_t)t*INNER + c;
    __nv_bfloat16 h0,l0,h1,l1,h2,l2,h3,l3;
    bf_split(o0,h0,l0); bf_split(o1,h1,l1); bf_split(o2,h2,l2); bf_split(o3,h3,l3);
    __nv_bfloat162 a; a.x=h0;a.y=h1; *(__nv_bfloat162*)(gh+base)=a;
    a.x=h2;a.y=h3; *(__nv_bfloat162*)(gh+base+2)=a;
    a.x=l0;a.y=l1; *(__nv_bfloat162*)(gl+base)=a;
    a.x=l2;a.y=l3; *(__nv_bfloat162*)(gl+base+2)=a;
}

// ---------------- launch ----------------
extern "C" void kernel_launch(void* const* d_in, const int* in_sizes, int n_in,
                              void* d_out, int out_size)
{
    const float* x      = (const float*)d_in[0];
    const float* w_in   = (const float*)d_in[1];
    const float* b_in   = (const float*)d_in[2];
    const float* ln1_w  = (const float*)d_in[3];
    const float* w_up   = (const float*)d_in[4];
    const float* b_up   = (const float*)d_in[5];
    const float* conv_w = (const float*)d_in[6];
    const float* conv_b = (const float*)d_in[7];
    const float* q_w    = (const float*)d_in[8];
    const float* q_b    = (const float*)d_in[9];
    const float* k_w    = (const float*)d_in[10];
    const float* k_b    = (const float*)d_in[11];
    const float* v_w    = (const float*)d_in[12];
    const float* v_b    = (const float*)d_in[13];
    const float* ig_w   = (const float*)d_in[14];
    const float* ig_b   = (const float*)d_in[15];
    const float* fg_w   = (const float*)d_in[16];
    const float* fg_b   = (const float*)d_in[17];
    const float* onorm_w= (const float*)d_in[18];
    const float* skipv  = (const float*)d_in[19];
    const float* w_down = (const float*)d_in[20];
    const float* b_down = (const float*)d_in[21];
    const float* post_w = (const float*)d_in[22];

    static float *p_hin=nullptr,*p_up,*p_xca,*p_v,*p_ig,*p_fg,
                 *p_cum,*p_m,*p_in2,*p_ps,*p_h,*p_yt;
    static __nv_bfloat16 *p_xh,*p_xl,*p_wiTh,*p_wiTl,*p_lnh,*p_lnl,*p_wupTh,*p_wupTl,
                 *p_qh,*p_ql,*p_kh,*p_kl,*p_vTh,*p_vTl,*p_Ch,*p_Cl,*p_gh,*p_gl,*p_wdTh,*p_wdTl;
    if (!p_hin) {
        cudaGetSymbolAddress((void**)&p_hin, g_hin);
        cudaGetSymbolAddress((void**)&p_up , g_up );
        cudaGetSymbolAddress((void**)&p_xca, g_xca);
        cudaGetSymbolAddress((void**)&p_v  , g_v  );
        cudaGetSymbolAddress((void**)&p_ig , g_ig );
        cudaGetSymbolAddress((void**)&p_fg , g_fg );
        cudaGetSymbolAddress((void**)&p_cum, g_cum);
        cudaGetSymbolAddress((void**)&p_m  , g_m  );
        cudaGetSymbolAddress((void**)&p_in2, g_in2);
        cudaGetSymbolAddress((void**)&p_ps , g_ps );
        cudaGetSymbolAddress((void**)&p_h  , g_h  );
        cudaGetSymbolAddress((void**)&p_yt , g_yt );
        cudaGetSymbolAddress((void**)&p_xh , g_xh );
        cudaGetSymbolAddress((void**)&p_xl , g_xl );
        cudaGetSymbolAddress((void**)&p_wiTh, g_wiTh);
        cudaGetSymbolAddress((void**)&p_wiTl, g_wiTl);
        cudaGetSymbolAddress((void**)&p_lnh, g_lnh);
        cudaGetSymbolAddress((void**)&p_lnl, g_lnl);
        cudaGetSymbolAddress((void**)&p_wupTh, g_wupTh);
        cudaGetSymbolAddress((void**)&p_wupTl, g_wupTl);
        cudaGetSymbolAddress((void**)&p_qh , g_qh );
        cudaGetSymbolAddress((void**)&p_ql , g_ql );
        cudaGetSymbolAddress((void**)&p_kh , g_kh );
        cudaGetSymbolAddress((void**)&p_kl , g_kl );
        cudaGetSymbolAddress((void**)&p_vTh, g_vTh);
        cudaGetSymbolAddress((void**)&p_vTl, g_vTl);
        cudaGetSymbolAddress((void**)&p_Ch , g_Ch );
        cudaGetSymbolAddress((void**)&p_Cl , g_Cl );
        cudaGetSymbolAddress((void**)&p_gh , g_gh );
        cudaGetSymbolAddress((void**)&p_gl , g_gl );
        cudaGetSymbolAddress((void**)&p_wdTh, g_wdTh);
        cudaGetSymbolAddress((void**)&p_wdTl, g_wdTl);
        cudaFuncSetAttribute(mma_gemm<0>, cudaFuncAttributeMaxDynamicSharedMemorySize, GEMM_SMEM);
        cudaFuncSetAttribute(mma_gemm<1>, cudaFuncAttributeMaxDynamicSharedMemorySize, GEMM_SMEM);
        cudaFuncSetAttribute(mma_gemm<2>, cudaFuncAttributeMaxDynamicSharedMemorySize, GEMM_SMEM);
        cudaFuncSetAttribute(mma_gemm<3>, cudaFuncAttributeMaxDynamicSharedMemorySize, GEMM_SMEM);
    }

    // 0) operand prep: split x, transpose+split weights
    split_kernel<<<(TCNT*IND/4 + 255)/256, 256>>>(x, p_xh, p_xl, TCNT*IND/4);
    tsplit_kernel<<<dim3(ED/32, IND/32), 256>>>(w_in,   p_wiTh,  p_wiTl,  IND,   ED);
    tsplit_kernel<<<dim3(UP2/32, ED/32), 256>>>(w_up,   p_wupTh, p_wupTl, ED,    UP2);
    tsplit_kernel<<<dim3(ED/32, INNER/32), 256>>>(w_down, p_wdTh, p_wdTl, INNER, ED);

    // 1) h_in = x @ w_in + b_in
    mma_gemm<0><<<dim3(ED/128, TCNT/128, 1), 256, GEMM_SMEM>>>(p_xh, p_xl, p_wiTh, p_wiTl,
        p_hin, nullptr, nullptr, IND, IND, IND, ED,
        b_in, nullptr, nullptr, nullptr, nullptr, nullptr);
    // 2) xn = LN(h_in)*ln1_w -> bf16 hi/lo
    ln_split_kernel<<<TCNT, 256>>>(p_hin, ln1_w, p_lnh, p_lnl);
    // 3) up = xn @ w_up + b_up
    mma_gemm<0><<<dim3(UP2/128, TCNT/128, 1), 256, GEMM_SMEM>>>(p_lnh, p_lnl, p_wupTh, p_wupTl,
        p_up, nullptr, nullptr, ED, ED, ED, UP2,
        b_up, nullptr, nullptr, nullptr, nullptr, nullptr);
    // 4) causal conv + SiLU
    conv_silu_kernel<<<(TCNT*INNER)/256, 256>>>(p_up, conv_w, conv_b, p_xca);
    // 5+6) fused block-diagonal q/k/v (+splits) + gate projections
    hwg_kernel<<<TCNT/GTOK, 512>>>(p_xca, p_up, q_w, q_b, k_w, k_b, v_w, v_b,
                                   ig_w, ig_b, fg_w, fg_b,
                                   p_v, p_qh, p_ql, p_kh, p_kl, p_ig, p_fg);
    // 7) per-head scans
    scan_kernel<<<ZB, 256>>>(p_fg, p_ig, p_cum, p_m);
    // 7b) v transpose+split per head
    vtrans_kernel<<<dim3(SEQ/32, DH/32, ZB), 256>>>(p_v, p_vTh, p_vTl);
    // 8) C = (q@k^T/sqrt(DH)) * decay, causal -> bf16 hi/lo + row partials (ps via Cf)
    mma_gemm<2><<<dim3(SEQ/128, SEQ/128, ZB), 256, GEMM_SMEM>>>(p_qh, p_ql, p_kh, p_kl,
        p_ps, p_Ch, p_Cl, DH, INNER, INNER, SEQ,
        nullptr, nullptr, p_cum, p_ig, p_m, nullptr);
    // 9) row normalizer from deterministic partials
    rowfix_kernel<<<(ZB*SEQ)/256, 256>>>(p_ps, p_m, p_in2);
    // 10) h = diag(invn) * C @ v
    mma_gemm<3><<<dim3(DH/128, SEQ/128, ZB), 256, GEMM_SMEM>>>(p_Ch, p_Cl, p_vTh, p_vTl,
        p_h, nullptr, nullptr, SEQ, SEQ, SEQ, DH,
        nullptr, nullptr, nullptr, nullptr, nullptr, p_in2);
    // 11) head-norm + skip + output gate -> bf16 hi/lo
    headnorm_gate_kernel<<<TCNT*NH, 128>>>(p_h, onorm_w, skipv, p_xca, p_up, p_gh, p_gl);
    // 12) yt = g @ w_down + b_down + h_in
    mma_gemm<1><<<dim3(ED/128, TCNT/128, 1), 256, GEMM_SMEM>>>(p_gh, p_gl, p_wdTh, p_wdTl,
        p_yt, nullptr, nullptr, INNER, INNER, INNER, ED,
        b_down, p_hin, nullptr, nullptr, nullptr, nullptr);
    // 13) out = LN(yt)*post_w
    ln_kernel<<<TCNT, 256>>>(p_yt, post_w, (float*)d_out);
}